// round 5
// baseline (speedup 1.0000x reference)
#include <cuda_runtime.h>
#include <cstdint>
#include <cfloat>

#define BATCH 64
#define UNUM  1024
#define ENUM  1024
#define UFD   512
#define EFD   256

__device__ float g_scale;
__device__ int   g_ne[BATCH];
__device__ float g_proj[(size_t)BATCH * UNUM * EFD];   // 64 MiB scratch

// ---------------------------------------------------------------------------
// helpers
// ---------------------------------------------------------------------------
__device__ __forceinline__ uint32_t packbf(float x0, float x1) {
    uint32_t r;
    asm("cvt.rn.bf16x2.f32 %0, %1, %2;" : "=r"(r) : "f"(x1), "f"(x0));
    return r;
}
__device__ __forceinline__ uint32_t lopack(uint32_t h, float x0, float x1) {
    float l0 = x0 - __uint_as_float(h << 16);
    float l1 = x1 - __uint_as_float(h & 0xffff0000u);
    return packbf(l0, l1);
}
__device__ __forceinline__ void mma_bf16(float* d, const uint32_t* a, const uint32_t* b) {
    asm volatile(
        "mma.sync.aligned.m16n8k16.row.col.f32.bf16.bf16.f32 "
        "{%0,%1,%2,%3}, {%4,%5,%6,%7}, {%8,%9}, {%0,%1,%2,%3};"
        : "+f"(d[0]), "+f"(d[1]), "+f"(d[2]), "+f"(d[3])
        : "r"(a[0]), "r"(a[1]), "r"(a[2]), "r"(a[3]), "r"(b[0]), "r"(b[1]));
}
__device__ __forceinline__ uint32_t smem_u32(const void* p) {
    uint32_t a;
    asm("{ .reg .u64 t; cvta.to.shared.u64 t, %1; cvt.u32.u64 %0, t; }" : "=r"(a) : "l"(p));
    return a;
}

// ---------------------------------------------------------------------------
// K0: scale = g / ||v||_F  +  robust num_enemy decode (int32 vs int64 layout)
// ---------------------------------------------------------------------------
__global__ __launch_bounds__(1024) void prep_kernel(const float* __restrict__ v,
                                                    const float* __restrict__ g,
                                                    const int* __restrict__ ne32) {
    __shared__ float wsum[32];
    int tid = threadIdx.x;
    float s = 0.f;
    for (int i = tid; i < EFD * UFD; i += 1024) { float x = v[i]; s += x * x; }
    #pragma unroll
    for (int o = 16; o; o >>= 1) s += __shfl_xor_sync(0xffffffffu, s, o);
    if ((tid & 31) == 0) wsum[tid >> 5] = s;
    __syncthreads();
    if (tid == 0) {
        float tot = 0.f;
        #pragma unroll
        for (int w = 0; w < 32; w++) tot += wsum[w];
        g_scale = g[0] / sqrtf(tot);
        bool is64 = true;
        for (int i = 0; i < 32; i++)
            if (ne32[2 * i + 1] != 0) { is64 = false; break; }
        for (int i = 0; i < BATCH; i++) g_ne[i] = is64 ? ne32[2 * i] : ne32[i];
    }
}

// ---------------------------------------------------------------------------
// proj GEMM (unchanged from R4, MODE-0 path only):
// g_proj = relu(g_scale * (ufeat @ v^T) + bias), tile 128x128, split bf16.
// ---------------------------------------------------------------------------
#define SMEM_BYTES (2 * 8192 * 4)   // 64 KB

__global__ __launch_bounds__(256) void proj_gemm(const float* __restrict__ Ag,
                                                 const float* __restrict__ Bg,
                                                 const float* __restrict__ bias) {
    extern __shared__ uint32_t smem[];
    const int t = threadIdx.x;
    const int warp = t >> 5, lane = t & 31;
    const int warpM = warp >> 2, warpN = warp & 3;
    const int m0 = blockIdx.y * 128, n0 = blockIdx.x * 128;
    constexpr int K = UFD;
    const float* Aq = Ag;
    const float* Bq = Bg;
    float* Cw = g_proj;

    float acc[4][4][4];
    #pragma unroll
    for (int i = 0; i < 4; i++)
        #pragma unroll
        for (int j = 0; j < 4; j++)
            #pragma unroll
            for (int r = 0; r < 4; r++) acc[i][j][r] = 0.f;

    float4 va[4], vb[4];
    constexpr int NB = K / 32;

    auto load_tile = [&](int kb) {
        const int k0 = kb * 32;
        #pragma unroll
        for (int i = 0; i < 4; i++) {
            int f = t + i * 256, row = f >> 3, q = f & 7;
            va[i] = *(const float4*)(Aq + (size_t)(m0 + row) * K + k0 + q * 4);
            vb[i] = *(const float4*)(Bq + (size_t)(n0 + row) * K + k0 + q * 4);
        }
    };
    auto store_tile = [&](int buf) {
        uint32_t* base = smem + buf * 8192;
        #pragma unroll
        for (int i = 0; i < 4; i++) {
            int f = t + i * 256, row = f >> 3, q = f & 7;
            const int kstep = q >> 2;
            const int hp = ((q & 3) * 2) & 3;
            const int kr = (q & 3) >> 1;
            {
                int m16 = row >> 4, r16 = row & 15;
                int reg = (r16 >> 3) + 2 * kr;
                uint32_t* p = base + ((kstep * 8 + m16) * 32 + (r16 & 7) * 4 + hp) * 4 + reg;
                uint32_t h0 = packbf(va[i].x, va[i].y);
                uint32_t h1 = packbf(va[i].z, va[i].w);
                p[0] = h0; p[4] = h1;
                p[2048 + 0] = lopack(h0, va[i].x, va[i].y);
                p[2048 + 4] = lopack(h1, va[i].z, va[i].w);
            }
            {
                int n8 = row >> 3;
                uint32_t* p = base + 4096 +
                    ((kstep * 16 + n8) * 32 + (row & 7) * 4 + hp) * 2 + kr;
                uint32_t h0 = packbf(vb[i].x, vb[i].y);
                uint32_t h1 = packbf(vb[i].z, vb[i].w);
                p[0] = h0; p[2] = h1;
                p[2048 + 0] = lopack(h0, vb[i].x, vb[i].y);
                p[2048 + 2] = lopack(h1, vb[i].z, vb[i].w);
            }
        }
    };
    auto compute = [&](int buf) {
        const uint32_t* sA = smem + buf * 8192;
        const uint32_t* sB = sA + 4096;
        #pragma unroll
        for (int ks = 0; ks < 2; ks++) {
            uint4 ah[4], al[4];
            uint2 bh[4], bl[4];
            #pragma unroll
            for (int mt = 0; mt < 4; mt++) {
                int idx = (ks * 8 + warpM * 4 + mt) * 32 + lane;
                ah[mt] = ((const uint4*)sA)[idx];
                al[mt] = ((const uint4*)(sA + 2048))[idx];
            }
            #pragma unroll
            for (int nt = 0; nt < 4; nt++) {
                int jdx = (ks * 16 + warpN * 4 + nt) * 32 + lane;
                bh[nt] = ((const uint2*)sB)[jdx];
                bl[nt] = ((const uint2*)(sB + 2048))[jdx];
            }
            #pragma unroll
            for (int mt = 0; mt < 4; mt++)
                #pragma unroll
                for (int nt = 0; nt < 4; nt++) {
                    mma_bf16(acc[mt][nt], (const uint32_t*)&ah[mt], (const uint32_t*)&bh[nt]);
                    mma_bf16(acc[mt][nt], (const uint32_t*)&ah[mt], (const uint32_t*)&bl[nt]);
                    mma_bf16(acc[mt][nt], (const uint32_t*)&al[mt], (const uint32_t*)&bh[nt]);
                }
        }
    };

    load_tile(0);
    store_tile(0);
    #pragma unroll 1
    for (int kb = 0; kb < NB; kb++) {
        __syncthreads();
        if (kb + 1 < NB) load_tile(kb + 1);
        compute(kb & 1);
        if (kb + 1 < NB) store_tile((kb + 1) & 1);
    }

    const int rbase = m0 + warpM * 64 + (lane >> 2);
    const int cbase = n0 + warpN * 32 + (lane & 3) * 2;
    const float s = g_scale;
    #pragma unroll
    for (int mt = 0; mt < 4; mt++) {
        int rL = rbase + mt * 16;
        #pragma unroll
        for (int nt = 0; nt < 4; nt++) {
            int cb = cbase + nt * 8;
            float b0 = bias[cb], b1 = bias[cb + 1];
            float2 o0, o1;
            o0.x = fmaxf(fmaf(s, acc[mt][nt][0], b0), 0.f);
            o0.y = fmaxf(fmaf(s, acc[mt][nt][1], b1), 0.f);
            o1.x = fmaxf(fmaf(s, acc[mt][nt][2], b0), 0.f);
            o1.y = fmaxf(fmaf(s, acc[mt][nt][3], b1), 0.f);
            *(float2*)(Cw + (size_t)rL * EFD + cb) = o0;
            *(float2*)(Cw + (size_t)(rL + 8) * EFD + cb) = o1;
        }
    }
}

// ---------------------------------------------------------------------------
// Fused logit GEMM + mask + row softmax.
// CTA: M=32, N=1024 (full row), 512 threads = 16 warps (2m x 8n), warp 16x128.
// A (proj 32x256) resident split-bf16 fragment-ordered; B (efeat) streamed
// per-kstep (16 k) fp32 via cp.async double buffer, converted at LDS time.
// SMEM words: A_hi[0,4096) A_lo[4096,8192) pmax[8192,8448) psum[8448,8704)
//             B0[9216,25600) B1[25600,41984)  -> 167936 bytes
// ---------------------------------------------------------------------------
#define FSMEM_BYTES (41984 * 4)

__global__ __launch_bounds__(512, 1) void logit_softmax(const float* __restrict__ efeat,
                                                        float* __restrict__ out) {
    extern __shared__ uint32_t sm[];
    const int t = threadIdx.x;
    const int warp = t >> 5, lane = t & 31;
    const int warpM = warp >> 3, warpN = warp & 7;
    const int z = blockIdx.y, m0 = blockIdx.x * 32;
    const float* Aq = g_proj + (size_t)z * UNUM * EFD;
    const float* Bq = efeat + (size_t)z * ENUM * EFD;
    float* Ow = out + (size_t)z * UNUM * ENUM;
    const uint32_t sbase = smem_u32(sm);

    // ---- A: load 32x256 fp32, convert to fragment-ordered split bf16 ----
    #pragma unroll
    for (int i = 0; i < 4; i++) {
        int f = t + i * 512;                 // float4 index, 64 per row
        int row = f >> 6, q = f & 63;        // q = k-quad (k = q*4)
        float4 va = *(const float4*)(Aq + (size_t)(m0 + row) * EFD + q * 4);
        int ks = q >> 2, qq = q & 3;
        int base = ((ks * 2 + (row >> 4)) * 32 + (row & 7) * 4 + ((qq * 2) & 3)) * 4
                   + ((row >> 3) & 1) + 2 * (qq >> 1);
        uint32_t h0 = packbf(va.x, va.y), h1 = packbf(va.z, va.w);
        sm[base] = h0;
        sm[base + 4] = h1;
        sm[4096 + base] = lopack(h0, va.x, va.y);
        sm[4096 + base + 4] = lopack(h1, va.z, va.w);
    }

    float acc[16][4];
    #pragma unroll
    for (int nt = 0; nt < 16; nt++)
        #pragma unroll
        for (int r = 0; r < 4; r++) acc[nt][r] = 0.f;

    // ---- B chunk issue: 1024 rows x 16 k fp32 -> smem [n][16] ----
    auto issueB = [&](int c) {
        const int k0 = c * 16;
        const uint32_t bb = sbase + (9216 + (c & 1) * 16384) * 4;
        #pragma unroll
        for (int i = 0; i < 8; i++) {
            int f4 = t + i * 512;
            int n = f4 >> 2, kq = (f4 & 3) * 4;
            const float* src = Bq + (size_t)n * EFD + k0 + kq;
            uint32_t dst = bb + (n * 16 + kq) * 4;
            asm volatile("cp.async.cg.shared.global [%0], [%1], 16;"
                         :: "r"(dst), "l"(src) : "memory");
        }
        asm volatile("cp.async.commit_group;" ::: "memory");
    };
    issueB(0);

    const int nb = warpN * 128 + (lane >> 2);
    const int kk = (lane & 3) * 2;

    #pragma unroll 1
    for (int c = 0; c < 16; c++) {
        asm volatile("cp.async.wait_group 0;" ::: "memory");
        __syncthreads();                      // chunk c visible; prev compute done
        if (c + 1 < 16) issueB(c + 1);        // overlaps compute(c)

        uint4 ah = ((const uint4*)sm)[(c * 2 + warpM) * 32 + lane];
        uint4 al = ((const uint4*)(sm + 4096))[(c * 2 + warpM) * 32 + lane];
        const float* Bbuf = (const float*)(sm + 9216 + (c & 1) * 16384);
        #pragma unroll
        for (int nt = 0; nt < 16; nt++) {
            const float* brow = Bbuf + (nb + nt * 8) * 16;
            float2 f0 = *(const float2*)(brow + kk);
            float2 f1 = *(const float2*)(brow + 8 + kk);
            uint32_t bh[2], bl[2];
            bh[0] = packbf(f0.x, f0.y);
            bh[1] = packbf(f1.x, f1.y);
            bl[0] = lopack(bh[0], f0.x, f0.y);
            bl[1] = lopack(bh[1], f1.x, f1.y);
            mma_bf16(acc[nt], (const uint32_t*)&ah, bh);
            mma_bf16(acc[nt], (const uint32_t*)&ah, bl);
            mma_bf16(acc[nt], (const uint32_t*)&al, bh);
        }
    }

    // ---- logits: scale + mask; row max ----
    const int ne = g_ne[z];
    float mlo = -FLT_MAX, mhi = -FLT_MAX;
    #pragma unroll
    for (int nt = 0; nt < 16; nt++) {
        int colb = warpN * 128 + nt * 8 + (lane & 3) * 2;
        float p0 = (colb >= ne) ? 1e9f : 0.f;
        float p1 = (colb + 1 >= ne) ? 1e9f : 0.f;
        acc[nt][0] = acc[nt][0] * 0.0625f - p0;
        acc[nt][1] = acc[nt][1] * 0.0625f - p1;
        acc[nt][2] = acc[nt][2] * 0.0625f - p0;
        acc[nt][3] = acc[nt][3] * 0.0625f - p1;
        mlo = fmaxf(mlo, fmaxf(acc[nt][0], acc[nt][1]));
        mhi = fmaxf(mhi, fmaxf(acc[nt][2], acc[nt][3]));
    }
    mlo = fmaxf(mlo, __shfl_xor_sync(0xffffffffu, mlo, 1));
    mlo = fmaxf(mlo, __shfl_xor_sync(0xffffffffu, mlo, 2));
    mhi = fmaxf(mhi, __shfl_xor_sync(0xffffffffu, mhi, 1));
    mhi = fmaxf(mhi, __shfl_xor_sync(0xffffffffu, mhi, 2));

    float* pmax = (float*)(sm + 8192);
    float* psum = (float*)(sm + 8448);
    const int rlo = warpM * 16 + (lane >> 2);
    if ((lane & 3) == 0) {
        pmax[rlo * 8 + warpN] = mlo;
        pmax[(rlo + 8) * 8 + warpN] = mhi;
    }
    __syncthreads();
    float rmlo = pmax[rlo * 8], rmhi = pmax[(rlo + 8) * 8];
    #pragma unroll
    for (int w = 1; w < 8; w++) {
        rmlo = fmaxf(rmlo, pmax[rlo * 8 + w]);
        rmhi = fmaxf(rmhi, pmax[(rlo + 8) * 8 + w]);
    }

    // ---- exp + row sum ----
    float slo = 0.f, shi = 0.f;
    #pragma unroll
    for (int nt = 0; nt < 16; nt++) {
        acc[nt][0] = __expf(acc[nt][0] - rmlo);
        acc[nt][1] = __expf(acc[nt][1] - rmlo);
        acc[nt][2] = __expf(acc[nt][2] - rmhi);
        acc[nt][3] = __expf(acc[nt][3] - rmhi);
        slo += acc[nt][0] + acc[nt][1];
        shi += acc[nt][2] + acc[nt][3];
    }
    slo += __shfl_xor_sync(0xffffffffu, slo, 1);
    slo += __shfl_xor_sync(0xffffffffu, slo, 2);
    shi += __shfl_xor_sync(0xffffffffu, shi, 1);
    shi += __shfl_xor_sync(0xffffffffu, shi, 2);
    if ((lane & 3) == 0) {
        psum[rlo * 8 + warpN] = slo;
        psum[(rlo + 8) * 8 + warpN] = shi;
    }
    __syncthreads();
    float tlo = 0.f, thi = 0.f;
    #pragma unroll
    for (int w = 0; w < 8; w++) {
        tlo += psum[rlo * 8 + w];
        thi += psum[(rlo + 8) * 8 + w];
    }
    const float ilo = 1.f / tlo, ihi = 1.f / thi;

    // ---- normalize + store ----
    float* rowlo = Ow + (size_t)(m0 + rlo) * ENUM;
    float* rowhi = Ow + (size_t)(m0 + rlo + 8) * ENUM;
    #pragma unroll
    for (int nt = 0; nt < 16; nt++) {
        int colb = warpN * 128 + nt * 8 + (lane & 3) * 2;
        float2 o0 = make_float2(acc[nt][0] * ilo, acc[nt][1] * ilo);
        float2 o1 = make_float2(acc[nt][2] * ihi, acc[nt][3] * ihi);
        *(float2*)(rowlo + colb) = o0;
        *(float2*)(rowhi + colb) = o1;
    }
}

// ---------------------------------------------------------------------------
extern "C" void kernel_launch(void* const* d_in, const int* in_sizes, int n_in,
                              void* d_out, int out_size) {
    const float* ufeat = (const float*)d_in[0];   // [64,1024,512]
    const float* efeat = (const float*)d_in[1];   // [64,1024,256]
    const int*   neptr = (const int*)d_in[2];     // [64] int32 or int64
    const float* v     = (const float*)d_in[3];   // [256,512]
    const float* g     = (const float*)d_in[4];   // scalar
    const float* bias  = (const float*)d_in[5];   // [256]
    float* out = (float*)d_out;                   // [64,1024,1024]

    cudaFuncSetAttribute(proj_gemm, cudaFuncAttributeMaxDynamicSharedMemorySize, SMEM_BYTES);
    cudaFuncSetAttribute(logit_softmax, cudaFuncAttributeMaxDynamicSharedMemorySize, FSMEM_BYTES);

    prep_kernel<<<1, 1024>>>(v, g, neptr);

    // proj: M=65536, N=256, K=512
    proj_gemm<<<dim3(EFD / 128, (BATCH * UNUM) / 128, 1), 256, SMEM_BYTES>>>(
        ufeat, v, bias);

    // fused logits + mask + softmax: per batch, 32 m-tiles of 32 rows
    logit_softmax<<<dim3(UNUM / 32, BATCH), 512, FSMEM_BYTES>>>(efeat, out);
}

// round 6
// speedup vs baseline: 1.0881x; 1.0881x over previous
#include <cuda_runtime.h>
#include <cstdint>
#include <cfloat>

#define BATCH 64
#define UNUM  1024
#define ENUM  1024
#define UFD   512
#define EFD   256

__device__ float g_scale;
__device__ float g_part[32];
__device__ int   g_ne[BATCH];
__device__ float g_proj[(size_t)BATCH * UNUM * EFD];            // 64 MiB
__device__ uint4 g_ebf[(size_t)BATCH * 16 * 128 * 32];          // 67 MiB, B frags

// ---------------------------------------------------------------------------
// helpers
// ---------------------------------------------------------------------------
__device__ __forceinline__ uint32_t packbf(float x0, float x1) {
    uint32_t r;
    asm("cvt.rn.bf16x2.f32 %0, %1, %2;" : "=r"(r) : "f"(x1), "f"(x0));
    return r;
}
__device__ __forceinline__ uint32_t lopack(uint32_t h, float x0, float x1) {
    float l0 = x0 - __uint_as_float(h << 16);
    float l1 = x1 - __uint_as_float(h & 0xffff0000u);
    return packbf(l0, l1);
}
__device__ __forceinline__ void mma_bf16(float* d, const uint32_t* a, const uint32_t* b) {
    asm volatile(
        "mma.sync.aligned.m16n8k16.row.col.f32.bf16.bf16.f32 "
        "{%0,%1,%2,%3}, {%4,%5,%6,%7}, {%8,%9}, {%0,%1,%2,%3};"
        : "+f"(d[0]), "+f"(d[1]), "+f"(d[2]), "+f"(d[3])
        : "r"(a[0]), "r"(a[1]), "r"(a[2]), "r"(a[3]), "r"(b[0]), "r"(b[1]));
}
__device__ __forceinline__ uint32_t smem_u32(const void* p) {
    uint32_t a;
    asm("{ .reg .u64 t; cvta.to.shared.u64 t, %1; cvt.u32.u64 %0, t; }" : "=r"(a) : "l"(p));
    return a;
}

// ---------------------------------------------------------------------------
// prep: ||v||^2 partials (deterministic fixed slots) + finalize + ne decode
// ---------------------------------------------------------------------------
__global__ __launch_bounds__(1024) void prep_partial(const float* __restrict__ v) {
    __shared__ float wsum[32];
    int tid = threadIdx.x, b = blockIdx.x;
    float s = 0.f;
    #pragma unroll
    for (int i = 0; i < 4; i++) {
        float x = v[b * 4096 + i * 1024 + tid];
        s += x * x;
    }
    #pragma unroll
    for (int o = 16; o; o >>= 1) s += __shfl_xor_sync(0xffffffffu, s, o);
    if ((tid & 31) == 0) wsum[tid >> 5] = s;
    __syncthreads();
    if (tid == 0) {
        float tot = 0.f;
        #pragma unroll
        for (int w = 0; w < 32; w++) tot += wsum[w];
        g_part[b] = tot;
    }
}
__global__ void prep_final(const float* __restrict__ g, const int* __restrict__ ne32) {
    if (threadIdx.x == 0) {
        float tot = 0.f;
        #pragma unroll
        for (int i = 0; i < 32; i++) tot += g_part[i];
        g_scale = g[0] / sqrtf(tot);
        bool is64 = true;
        for (int i = 0; i < 32; i++)
            if (ne32[2 * i + 1] != 0) { is64 = false; break; }
        for (int i = 0; i < BATCH; i++) g_ne[i] = is64 ? ne32[2 * i] : ne32[i];
    }
}

// ---------------------------------------------------------------------------
// econv: efeat [z][n][256] fp32 -> g_ebf fragment-ordered split bf16.
// Layout: [z][chunk c(16)][n8(128)][lane(32)] uint4 {hi_r0, hi_r1, lo_r0, lo_r1}
// where lane = (n%8)*4 + (k%8)/2, r0: k in [c*16, c*16+8), r1: +8.
// ---------------------------------------------------------------------------
__global__ __launch_bounds__(256) void econv(const float* __restrict__ efeat) {
    uint32_t gid = blockIdx.x * 256 + threadIdx.x;     // 4,194,304 total
    int lane = gid & 31;
    int n8   = (gid >> 5) & 127;
    int c    = (gid >> 12) & 15;
    int z    = gid >> 16;
    int n    = n8 * 8 + (lane >> 2);
    int k0   = c * 16 + (lane & 3) * 2;
    const float* src = efeat + ((size_t)z * ENUM + n) * EFD;
    float2 f0 = *(const float2*)(src + k0);
    float2 f1 = *(const float2*)(src + k0 + 8);
    uint4 o;
    o.x = packbf(f0.x, f0.y);
    o.y = packbf(f1.x, f1.y);
    o.z = lopack(o.x, f0.x, f0.y);
    o.w = lopack(o.y, f1.x, f1.y);
    g_ebf[gid] = o;
}

// ---------------------------------------------------------------------------
// proj GEMM (validated R4 path): g_proj = relu(g_scale*(ufeat@v^T)+bias),
// tile 128x128, BK=32, split bf16, 256 threads.
// ---------------------------------------------------------------------------
#define SMEM_BYTES (2 * 8192 * 4)   // 64 KB

__global__ __launch_bounds__(256) void proj_gemm(const float* __restrict__ Ag,
                                                 const float* __restrict__ Bg,
                                                 const float* __restrict__ bias) {
    extern __shared__ uint32_t smem[];
    const int t = threadIdx.x;
    const int warp = t >> 5, lane = t & 31;
    const int warpM = warp >> 2, warpN = warp & 3;
    const int m0 = blockIdx.y * 128, n0 = blockIdx.x * 128;
    constexpr int K = UFD;
    const float* Aq = Ag;
    const float* Bq = Bg;
    float* Cw = g_proj;

    float acc[4][4][4];
    #pragma unroll
    for (int i = 0; i < 4; i++)
        #pragma unroll
        for (int j = 0; j < 4; j++)
            #pragma unroll
            for (int r = 0; r < 4; r++) acc[i][j][r] = 0.f;

    float4 va[4], vb[4];
    constexpr int NB = K / 32;

    auto load_tile = [&](int kb) {
        const int k0 = kb * 32;
        #pragma unroll
        for (int i = 0; i < 4; i++) {
            int f = t + i * 256, row = f >> 3, q = f & 7;
            va[i] = *(const float4*)(Aq + (size_t)(m0 + row) * K + k0 + q * 4);
            vb[i] = *(const float4*)(Bq + (size_t)(n0 + row) * K + k0 + q * 4);
        }
    };
    auto store_tile = [&](int buf) {
        uint32_t* base = smem + buf * 8192;
        #pragma unroll
        for (int i = 0; i < 4; i++) {
            int f = t + i * 256, row = f >> 3, q = f & 7;
            const int kstep = q >> 2;
            const int hp = ((q & 3) * 2) & 3;
            const int kr = (q & 3) >> 1;
            {
                int m16 = row >> 4, r16 = row & 15;
                int reg = (r16 >> 3) + 2 * kr;
                uint32_t* p = base + ((kstep * 8 + m16) * 32 + (r16 & 7) * 4 + hp) * 4 + reg;
                uint32_t h0 = packbf(va[i].x, va[i].y);
                uint32_t h1 = packbf(va[i].z, va[i].w);
                p[0] = h0; p[4] = h1;
                p[2048 + 0] = lopack(h0, va[i].x, va[i].y);
                p[2048 + 4] = lopack(h1, va[i].z, va[i].w);
            }
            {
                int n8 = row >> 3;
                uint32_t* p = base + 4096 +
                    ((kstep * 16 + n8) * 32 + (row & 7) * 4 + hp) * 2 + kr;
                uint32_t h0 = packbf(vb[i].x, vb[i].y);
                uint32_t h1 = packbf(vb[i].z, vb[i].w);
                p[0] = h0; p[2] = h1;
                p[2048 + 0] = lopack(h0, vb[i].x, vb[i].y);
                p[2048 + 2] = lopack(h1, vb[i].z, vb[i].w);
            }
        }
    };
    auto compute = [&](int buf) {
        const uint32_t* sA = smem + buf * 8192;
        const uint32_t* sB = sA + 4096;
        #pragma unroll
        for (int ks = 0; ks < 2; ks++) {
            uint4 ah[4], al[4];
            uint2 bh[4], bl[4];
            #pragma unroll
            for (int mt = 0; mt < 4; mt++) {
                int idx = (ks * 8 + warpM * 4 + mt) * 32 + lane;
                ah[mt] = ((const uint4*)sA)[idx];
                al[mt] = ((const uint4*)(sA + 2048))[idx];
            }
            #pragma unroll
            for (int nt = 0; nt < 4; nt++) {
                int jdx = (ks * 16 + warpN * 4 + nt) * 32 + lane;
                bh[nt] = ((const uint2*)sB)[jdx];
                bl[nt] = ((const uint2*)(sB + 2048))[jdx];
            }
            #pragma unroll
            for (int mt = 0; mt < 4; mt++)
                #pragma unroll
                for (int nt = 0; nt < 4; nt++) {
                    mma_bf16(acc[mt][nt], (const uint32_t*)&ah[mt], (const uint32_t*)&bh[nt]);
                    mma_bf16(acc[mt][nt], (const uint32_t*)&ah[mt], (const uint32_t*)&bl[nt]);
                    mma_bf16(acc[mt][nt], (const uint32_t*)&al[mt], (const uint32_t*)&bh[nt]);
                }
        }
    };

    load_tile(0);
    store_tile(0);
    #pragma unroll 1
    for (int kb = 0; kb < NB; kb++) {
        __syncthreads();
        if (kb + 1 < NB) load_tile(kb + 1);
        compute(kb & 1);
        if (kb + 1 < NB) store_tile((kb + 1) & 1);
    }

    const int rbase = m0 + warpM * 64 + (lane >> 2);
    const int cbase = n0 + warpN * 32 + (lane & 3) * 2;
    const float s = g_scale;
    #pragma unroll
    for (int mt = 0; mt < 4; mt++) {
        int rL = rbase + mt * 16;
        #pragma unroll
        for (int nt = 0; nt < 4; nt++) {
            int cb = cbase + nt * 8;
            float b0 = bias[cb], b1 = bias[cb + 1];
            float2 o0, o1;
            o0.x = fmaxf(fmaf(s, acc[mt][nt][0], b0), 0.f);
            o0.y = fmaxf(fmaf(s, acc[mt][nt][1], b1), 0.f);
            o1.x = fmaxf(fmaf(s, acc[mt][nt][2], b0), 0.f);
            o1.y = fmaxf(fmaf(s, acc[mt][nt][3], b1), 0.f);
            *(float2*)(Cw + (size_t)rL * EFD + cb) = o0;
            *(float2*)(Cw + (size_t)(rL + 8) * EFD + cb) = o1;
        }
    }
}

// ---------------------------------------------------------------------------
// Fused logit GEMM + mask + row softmax.
// CTA: M=32, N=1024, 512 threads (2m x 8n warps), warp tile 16x128.
// A converted once at start (split bf16, fragment order).
// B streamed as PRE-CONVERTED fragments from g_ebf via cp.async (64KB/chunk,
// double buffered). Inner loop: 1 uint4 LDS + 3 MMAs per B fragment.
// SMEM words: A_hi[0,4096) A_lo[4096,8192) pmax[8192,8448) psum[8448,8704)
//             B0[9216,25600) B1[25600,41984)
// ---------------------------------------------------------------------------
#define FSMEM_BYTES (41984 * 4)

__global__ __launch_bounds__(512, 1) void logit_softmax(const float* __restrict__ efeat_unused,
                                                        float* __restrict__ out) {
    extern __shared__ uint32_t sm[];
    const int t = threadIdx.x;
    const int warp = t >> 5, lane = t & 31;
    const int warpM = warp >> 3, warpN = warp & 7;
    const int z = blockIdx.y, m0 = blockIdx.x * 32;
    const float* Aq = g_proj + (size_t)z * UNUM * EFD;
    float* Ow = out + (size_t)z * UNUM * ENUM;
    const uint32_t sbase = smem_u32(sm);

    // ---- A: load 32x256 fp32, convert once to fragment-ordered split bf16 ----
    #pragma unroll
    for (int i = 0; i < 4; i++) {
        int f = t + i * 512;
        int row = f >> 6, q = f & 63;
        float4 va = *(const float4*)(Aq + (size_t)(m0 + row) * EFD + q * 4);
        int ks = q >> 2, qq = q & 3;
        int base = ((ks * 2 + (row >> 4)) * 32 + (row & 7) * 4 + ((qq * 2) & 3)) * 4
                   + ((row >> 3) & 1) + 2 * (qq >> 1);
        uint32_t h0 = packbf(va.x, va.y), h1 = packbf(va.z, va.w);
        sm[base] = h0;
        sm[base + 4] = h1;
        sm[4096 + base] = lopack(h0, va.x, va.y);
        sm[4096 + base + 4] = lopack(h1, va.z, va.w);
    }

    float acc[16][4];
    #pragma unroll
    for (int nt = 0; nt < 16; nt++)
        #pragma unroll
        for (int r = 0; r < 4; r++) acc[nt][r] = 0.f;

    // ---- B chunk issue: pre-converted fragments, 4096 uint4 per chunk ----
    const uint4* ebase = g_ebf + (size_t)z * 16 * 4096;
    auto issueB = [&](int c) {
        const uint4* src = ebase + c * 4096;
        const uint32_t bb = sbase + (9216 + (c & 1) * 16384) * 4;
        #pragma unroll
        for (int i = 0; i < 8; i++) {
            int f4 = t + i * 512;
            asm volatile("cp.async.cg.shared.global [%0], [%1], 16;"
                         :: "r"(bb + f4 * 16), "l"(src + f4) : "memory");
        }
        asm volatile("cp.async.commit_group;" ::: "memory");
    };
    issueB(0);

    #pragma unroll 1
    for (int c = 0; c < 16; c++) {
        asm volatile("cp.async.wait_group 0;" ::: "memory");
        __syncthreads();
        if (c + 1 < 16) issueB(c + 1);

        uint4 ah = ((const uint4*)sm)[(c * 2 + warpM) * 32 + lane];
        uint4 al = ((const uint4*)(sm + 4096))[(c * 2 + warpM) * 32 + lane];
        const uint4* Bu = (const uint4*)(sm + 9216 + (c & 1) * 16384);
        #pragma unroll
        for (int nt = 0; nt < 16; nt++) {
            uint4 b = Bu[(warpN * 16 + nt) * 32 + lane];
            uint32_t bh[2] = { b.x, b.y };
            uint32_t bl[2] = { b.z, b.w };
            mma_bf16(acc[nt], (const uint32_t*)&ah, bh);
            mma_bf16(acc[nt], (const uint32_t*)&ah, bl);
            mma_bf16(acc[nt], (const uint32_t*)&al, bh);
        }
    }

    // ---- logits: scale + mask; row max ----
    const int ne = g_ne[z];
    float mlo = -FLT_MAX, mhi = -FLT_MAX;
    #pragma unroll
    for (int nt = 0; nt < 16; nt++) {
        int colb = warpN * 128 + nt * 8 + (lane & 3) * 2;
        float p0 = (colb >= ne) ? 1e9f : 0.f;
        float p1 = (colb + 1 >= ne) ? 1e9f : 0.f;
        acc[nt][0] = acc[nt][0] * 0.0625f - p0;
        acc[nt][1] = acc[nt][1] * 0.0625f - p1;
        acc[nt][2] = acc[nt][2] * 0.0625f - p0;
        acc[nt][3] = acc[nt][3] * 0.0625f - p1;
        mlo = fmaxf(mlo, fmaxf(acc[nt][0], acc[nt][1]));
        mhi = fmaxf(mhi, fmaxf(acc[nt][2], acc[nt][3]));
    }
    mlo = fmaxf(mlo, __shfl_xor_sync(0xffffffffu, mlo, 1));
    mlo = fmaxf(mlo, __shfl_xor_sync(0xffffffffu, mlo, 2));
    mhi = fmaxf(mhi, __shfl_xor_sync(0xffffffffu, mhi, 1));
    mhi = fmaxf(mhi, __shfl_xor_sync(0xffffffffu, mhi, 2));

    float* pmax = (float*)(sm + 8192);
    float* psum = (float*)(sm + 8448);
    const int rlo = warpM * 16 + (lane >> 2);
    if ((lane & 3) == 0) {
        pmax[rlo * 8 + warpN] = mlo;
        pmax[(rlo + 8) * 8 + warpN] = mhi;
    }
    __syncthreads();
    float rmlo = pmax[rlo * 8], rmhi = pmax[(rlo + 8) * 8];
    #pragma unroll
    for (int w = 1; w < 8; w++) {
        rmlo = fmaxf(rmlo, pmax[rlo * 8 + w]);
        rmhi = fmaxf(rmhi, pmax[(rlo + 8) * 8 + w]);
    }

    // ---- exp + row sum ----
    float slo = 0.f, shi = 0.f;
    #pragma unroll
    for (int nt = 0; nt < 16; nt++) {
        acc[nt][0] = __expf(acc[nt][0] - rmlo);
        acc[nt][1] = __expf(acc[nt][1] - rmlo);
        acc[nt][2] = __expf(acc[nt][2] - rmhi);
        acc[nt][3] = __expf(acc[nt][3] - rmhi);
        slo += acc[nt][0] + acc[nt][1];
        shi += acc[nt][2] + acc[nt][3];
    }
    slo += __shfl_xor_sync(0xffffffffu, slo, 1);
    slo += __shfl_xor_sync(0xffffffffu, slo, 2);
    shi += __shfl_xor_sync(0xffffffffu, shi, 1);
    shi += __shfl_xor_sync(0xffffffffu, shi, 2);
    if ((lane & 3) == 0) {
        psum[rlo * 8 + warpN] = slo;
        psum[(rlo + 8) * 8 + warpN] = shi;
    }
    __syncthreads();
    float tlo = 0.f, thi = 0.f;
    #pragma unroll
    for (int w = 0; w < 8; w++) {
        tlo += psum[rlo * 8 + w];
        thi += psum[(rlo + 8) * 8 + w];
    }
    const float ilo = 1.f / tlo, ihi = 1.f / thi;

    // ---- normalize + store ----
    float* rowlo = Ow + (size_t)(m0 + rlo) * ENUM;
    float* rowhi = Ow + (size_t)(m0 + rlo + 8) * ENUM;
    #pragma unroll
    for (int nt = 0; nt < 16; nt++) {
        int colb = warpN * 128 + nt * 8 + (lane & 3) * 2;
        float2 o0 = make_float2(acc[nt][0] * ilo, acc[nt][1] * ilo);
        float2 o1 = make_float2(acc[nt][2] * ihi, acc[nt][3] * ihi);
        *(float2*)(rowlo + colb) = o0;
        *(float2*)(rowhi + colb) = o1;
    }
}

// ---------------------------------------------------------------------------
extern "C" void kernel_launch(void* const* d_in, const int* in_sizes, int n_in,
                              void* d_out, int out_size) {
    const float* ufeat = (const float*)d_in[0];   // [64,1024,512]
    const float* efeat = (const float*)d_in[1];   // [64,1024,256]
    const int*   neptr = (const int*)d_in[2];     // [64] int32 or int64
    const float* v     = (const float*)d_in[3];   // [256,512]
    const float* g     = (const float*)d_in[4];   // scalar
    const float* bias  = (const float*)d_in[5];   // [256]
    float* out = (float*)d_out;                   // [64,1024,1024]

    cudaFuncSetAttribute(proj_gemm, cudaFuncAttributeMaxDynamicSharedMemorySize, SMEM_BYTES);
    cudaFuncSetAttribute(logit_softmax, cudaFuncAttributeMaxDynamicSharedMemorySize, FSMEM_BYTES);

    prep_partial<<<32, 1024>>>(v);
    prep_final<<<1, 32>>>(g, neptr);

    // B fragments for the fused gemm (overlaps nothing, but cheap: ~18us)
    econv<<<16384, 256>>>(efeat);

    // proj: M=65536, N=256, K=512
    proj_gemm<<<dim3(EFD / 128, (BATCH * UNUM) / 128, 1), 256, SMEM_BYTES>>>(
        ufeat, v, bias);

    // fused logits + mask + softmax
    logit_softmax<<<dim3(UNUM / 32, BATCH), 512, FSMEM_BYTES>>>(efeat, out);
}

// round 7
// speedup vs baseline: 1.1257x; 1.0346x over previous
#include <cuda_runtime.h>
#include <cstdint>
#include <cfloat>

#define BATCH 64
#define UNUM  1024
#define ENUM  1024
#define UFD   512
#define EFD   256

__device__ float g_scale;
__device__ float g_part[32];
__device__ int   g_ne[BATCH];
__device__ float g_proj[(size_t)BATCH * UNUM * EFD];              // 64 MiB fp32
__device__ uint4 g_ebf[(size_t)BATCH * 16 * 128 * 32];            // efeat B-frags
__device__ uint4 g_ubf[(size_t)4096 * 32 * 32 * 2];               // ufeat A-frags hi/lo
__device__ uint4 g_vbf[(size_t)32 * 32 * 32];                     // v B-frags

// ---------------------------------------------------------------------------
// helpers
// ---------------------------------------------------------------------------
__device__ __forceinline__ uint32_t packbf(float x0, float x1) {
    uint32_t r;
    asm("cvt.rn.bf16x2.f32 %0, %1, %2;" : "=r"(r) : "f"(x1), "f"(x0));
    return r;
}
__device__ __forceinline__ uint32_t lopack(uint32_t h, float x0, float x1) {
    float l0 = x0 - __uint_as_float(h << 16);
    float l1 = x1 - __uint_as_float(h & 0xffff0000u);
    return packbf(l0, l1);
}
__device__ __forceinline__ void mma_bf16(float* d, const uint32_t* a, const uint32_t* b) {
    asm volatile(
        "mma.sync.aligned.m16n8k16.row.col.f32.bf16.bf16.f32 "
        "{%0,%1,%2,%3}, {%4,%5,%6,%7}, {%8,%9}, {%0,%1,%2,%3};"
        : "+f"(d[0]), "+f"(d[1]), "+f"(d[2]), "+f"(d[3])
        : "r"(a[0]), "r"(a[1]), "r"(a[2]), "r"(a[3]), "r"(b[0]), "r"(b[1]));
}
__device__ __forceinline__ uint32_t smem_u32(const void* p) {
    uint32_t a;
    asm("{ .reg .u64 t; cvta.to.shared.u64 t, %1; cvt.u32.u64 %0, t; }" : "=r"(a) : "l"(p));
    return a;
}
#define CP16(dst, src) \
    asm volatile("cp.async.cg.shared.global [%0], [%1], 16;" :: "r"(dst), "l"(src) : "memory")
#define CP_COMMIT() asm volatile("cp.async.commit_group;" ::: "memory")
#define CP_WAIT1()  asm volatile("cp.async.wait_group 1;" ::: "memory")
#define CP_WAIT0()  asm volatile("cp.async.wait_group 0;" ::: "memory")

// ---------------------------------------------------------------------------
// prep: ||v||^2 partials + finalize + ne decode
// ---------------------------------------------------------------------------
__global__ __launch_bounds__(1024) void prep_partial(const float* __restrict__ v) {
    __shared__ float wsum[32];
    int tid = threadIdx.x, b = blockIdx.x;
    float s = 0.f;
    #pragma unroll
    for (int i = 0; i < 4; i++) {
        float x = v[b * 4096 + i * 1024 + tid];
        s += x * x;
    }
    #pragma unroll
    for (int o = 16; o; o >>= 1) s += __shfl_xor_sync(0xffffffffu, s, o);
    if ((tid & 31) == 0) wsum[tid >> 5] = s;
    __syncthreads();
    if (tid == 0) {
        float tot = 0.f;
        #pragma unroll
        for (int w = 0; w < 32; w++) tot += wsum[w];
        g_part[b] = tot;
    }
}
__global__ void prep_final(const float* __restrict__ g, const int* __restrict__ ne32) {
    if (threadIdx.x == 0) {
        float tot = 0.f;
        #pragma unroll
        for (int i = 0; i < 32; i++) tot += g_part[i];
        g_scale = g[0] / sqrtf(tot);
        bool is64 = true;
        for (int i = 0; i < 32; i++)
            if (ne32[2 * i + 1] != 0) { is64 = false; break; }
        for (int i = 0; i < BATCH; i++) g_ne[i] = is64 ? ne32[2 * i] : ne32[i];
    }
}

// ---------------------------------------------------------------------------
// econv: efeat -> B-fragment split bf16 (validated R6 layout).
// [z][c(16)][n8(128)][lane(32)] uint4 {hi_r0, hi_r1, lo_r0, lo_r1}
// ---------------------------------------------------------------------------
__global__ __launch_bounds__(256) void econv(const float* __restrict__ efeat) {
    uint32_t gid = blockIdx.x * 256 + threadIdx.x;
    int lane = gid & 31;
    int n8   = (gid >> 5) & 127;
    int c    = (gid >> 12) & 15;
    int z    = gid >> 16;
    int n    = n8 * 8 + (lane >> 2);
    int k0   = c * 16 + (lane & 3) * 2;
    const float* src = efeat + ((size_t)z * ENUM + n) * EFD;
    float2 f0 = *(const float2*)(src + k0);
    float2 f1 = *(const float2*)(src + k0 + 8);
    uint4 o;
    o.x = packbf(f0.x, f0.y);
    o.y = packbf(f1.x, f1.y);
    o.z = lopack(o.x, f0.x, f0.y);
    o.w = lopack(o.y, f1.x, f1.y);
    g_ebf[gid] = o;
}

// ---------------------------------------------------------------------------
// vconv: v [256][512] -> B-fragments, [c(32)][n8(32)][lane] (same convention)
// ---------------------------------------------------------------------------
__global__ __launch_bounds__(256) void vconv(const float* __restrict__ v) {
    uint32_t gid = blockIdx.x * 256 + threadIdx.x;   // 32768
    int lane = gid & 31;
    int n8   = (gid >> 5) & 31;
    int c    = gid >> 10;
    int n    = n8 * 8 + (lane >> 2);
    int k0   = c * 16 + (lane & 3) * 2;
    const float* src = v + (size_t)n * UFD;
    float2 f0 = *(const float2*)(src + k0);
    float2 f1 = *(const float2*)(src + k0 + 8);
    uint4 o;
    o.x = packbf(f0.x, f0.y);
    o.y = packbf(f1.x, f1.y);
    o.z = lopack(o.x, f0.x, f0.y);
    o.w = lopack(o.y, f1.x, f1.y);
    g_vbf[gid] = o;
}

// ---------------------------------------------------------------------------
// uconv: ufeat [65536][512] -> A-fragments (m16n8k16 A layout, hi/lo pair).
// index gid = (m16*32 + c)*32 + lane; g_ubf[gid*2]=hi{a0..a3}, [gid*2+1]=lo.
// a0:(r=l>>2, k=(l&3)*2), a1:(r+8, k), a2:(r, k+8), a3:(r+8, k+8)
// ---------------------------------------------------------------------------
__global__ __launch_bounds__(256) void uconv(const float* __restrict__ uf) {
    uint32_t gid = blockIdx.x * 256 + threadIdx.x;   // 4,194,304
    int lane = gid & 31;
    int c    = (gid >> 5) & 31;
    int m16  = gid >> 10;
    int r    = m16 * 16 + (lane >> 2);
    int k0   = c * 16 + (lane & 3) * 2;
    const float* s0 = uf + (size_t)r * UFD;
    const float* s1 = uf + (size_t)(r + 8) * UFD;
    float2 a0 = *(const float2*)(s0 + k0);
    float2 a1 = *(const float2*)(s1 + k0);
    float2 a2 = *(const float2*)(s0 + k0 + 8);
    float2 a3 = *(const float2*)(s1 + k0 + 8);
    uint4 hi, lo;
    hi.x = packbf(a0.x, a0.y); hi.y = packbf(a1.x, a1.y);
    hi.z = packbf(a2.x, a2.y); hi.w = packbf(a3.x, a3.y);
    lo.x = lopack(hi.x, a0.x, a0.y); lo.y = lopack(hi.y, a1.x, a1.y);
    lo.z = lopack(hi.z, a2.x, a2.y); lo.w = lopack(hi.w, a3.x, a3.y);
    g_ubf[(size_t)gid * 2 + 0] = hi;
    g_ubf[(size_t)gid * 2 + 1] = lo;
}

// ---------------------------------------------------------------------------
// proj GEMM (pure MMA): g_proj = relu(g_scale*(ufeat@v^T)+bias).
// Tile 128x128, 256 thr (2m x 4n warps, warp 64x32), 3-stage cp.async.
// Stage (1024 uint4): A_hi [0,256) idx=m16l*32+lane, A_lo [256,512),
//                     B [512,1024) idx=n8l*32+lane.
// ---------------------------------------------------------------------------
#define PSMEM_BYTES (3 * 1024 * 16)   // 48 KB

__global__ __launch_bounds__(256, 2) void proj_gemm(const float* __restrict__ bias) {
    extern __shared__ uint4 su[];
    const uint32_t sbase = smem_u32(su);
    const int t = threadIdx.x;
    const int warp = t >> 5, lane = t & 31;
    const int warpM = warp >> 2, warpN = warp & 3;
    const int m0 = blockIdx.y * 128, n0 = blockIdx.x * 128;
    const int m16base = blockIdx.y * 8;
    const int n8base = blockIdx.x * 16;

    float acc[4][4][4];
    #pragma unroll
    for (int i = 0; i < 4; i++)
        #pragma unroll
        for (int j = 0; j < 4; j++)
            #pragma unroll
            for (int r = 0; r < 4; r++) acc[i][j][r] = 0.f;

    constexpr int NCH = UFD / 16;   // 32

    auto issue = [&](int c) {
        const int s = ((unsigned)c) % 3;
        const uint32_t stb = sbase + s * 16384;
        #pragma unroll
        for (int i = 0; i < 2; i++) {          // A: 512 uint4
            int f = t + i * 256;
            int h = f >> 8, m16l = (f >> 5) & 7, ln = f & 31;
            const uint4* src = g_ubf + ((size_t)((m16base + m16l) * 32 + c) * 32 + ln) * 2 + h;
            CP16(stb + f * 16, src);
        }
        #pragma unroll
        for (int i = 0; i < 2; i++) {          // B: 512 uint4
            int f = t + i * 256;
            int n8l = f >> 5, ln = f & 31;
            const uint4* src = g_vbf + (size_t)(c * 32 + n8base + n8l) * 32 + ln;
            CP16(stb + (512 + f) * 16, src);
        }
        CP_COMMIT();
    };

    issue(0);
    issue(1);
    #pragma unroll 1
    for (int c = 0; c < NCH; c++) {
        if (c == NCH - 1) CP_WAIT0(); else CP_WAIT1();
        __syncthreads();
        if (c + 2 < NCH) issue(c + 2);

        const uint4* st = su + ((unsigned)c % 3) * 1024;
        uint4 ah[4], al[4], bb[4];
        #pragma unroll
        for (int mt = 0; mt < 4; mt++) {
            int idx = (warpM * 4 + mt) * 32 + lane;
            ah[mt] = st[idx];
            al[mt] = st[256 + idx];
        }
        #pragma unroll
        for (int nt = 0; nt < 4; nt++)
            bb[nt] = st[512 + (warpN * 4 + nt) * 32 + lane];
        #pragma unroll
        for (int mt = 0; mt < 4; mt++)
            #pragma unroll
            for (int nt = 0; nt < 4; nt++) {
                uint32_t bh[2] = { bb[nt].x, bb[nt].y };
                uint32_t bl[2] = { bb[nt].z, bb[nt].w };
                mma_bf16(acc[mt][nt], (const uint32_t*)&ah[mt], bh);
                mma_bf16(acc[mt][nt], (const uint32_t*)&ah[mt], bl);
                mma_bf16(acc[mt][nt], (const uint32_t*)&al[mt], bh);
            }
    }

    // epilogue (validated R6 mapping)
    const int rbase = m0 + warpM * 64 + (lane >> 2);
    const int cbase = n0 + warpN * 32 + (lane & 3) * 2;
    const float s = g_scale;
    #pragma unroll
    for (int mt = 0; mt < 4; mt++) {
        int rL = rbase + mt * 16;
        #pragma unroll
        for (int nt = 0; nt < 4; nt++) {
            int cb = cbase + nt * 8;
            float b0 = bias[cb], b1 = bias[cb + 1];
            float2 o0, o1;
            o0.x = fmaxf(fmaf(s, acc[mt][nt][0], b0), 0.f);
            o0.y = fmaxf(fmaf(s, acc[mt][nt][1], b1), 0.f);
            o1.x = fmaxf(fmaf(s, acc[mt][nt][2], b0), 0.f);
            o1.y = fmaxf(fmaf(s, acc[mt][nt][3], b1), 0.f);
            *(float2*)(g_proj + (size_t)rL * EFD + cb) = o0;
            *(float2*)(g_proj + (size_t)(rL + 8) * EFD + cb) = o1;
        }
    }
}

// ---------------------------------------------------------------------------
// Fused logit GEMM + mask + softmax.
// CTA M=32, N=1024, 512 thr = 16 warps (1m x 16n), warp tile 32x64.
// A (32x256) converted once into smem (R6-validated layout); B streamed from
// g_ebf, 3-stage. Softmax scratch reuses B stage 0 after compute.
// SMEM words: A_hi [0,4096) A_lo [4096,8192) B stages [8192 + s*16384)
// ---------------------------------------------------------------------------
#define FSMEM_BYTES ((8192 + 3 * 16384) * 4)   // 229376

__global__ __launch_bounds__(512, 1) void logit_softmax(float* __restrict__ out) {
    extern __shared__ uint32_t sm[];
    const uint32_t sbase = smem_u32(sm);
    const int t = threadIdx.x;
    const int warp = t >> 5, lane = t & 31;
    const int z = blockIdx.y, m0 = blockIdx.x * 32;
    const float* Aq = g_proj + (size_t)z * UNUM * EFD;
    float* Ow = out + (size_t)z * UNUM * ENUM;

    // ---- A: load 32x256 fp32, convert once (R6-validated formula) ----
    #pragma unroll
    for (int i = 0; i < 4; i++) {
        int f = t + i * 512;
        int row = f >> 6, q = f & 63;
        float4 va = *(const float4*)(Aq + (size_t)(m0 + row) * EFD + q * 4);
        int ks = q >> 2, qq = q & 3;
        int base = ((ks * 2 + (row >> 4)) * 32 + (row & 7) * 4 + ((qq * 2) & 3)) * 4
                   + ((row >> 3) & 1) + 2 * (qq >> 1);
        uint32_t h0 = packbf(va.x, va.y), h1 = packbf(va.z, va.w);
        sm[base] = h0;
        sm[base + 4] = h1;
        sm[4096 + base] = lopack(h0, va.x, va.y);
        sm[4096 + base + 4] = lopack(h1, va.z, va.w);
    }

    float acc[2][8][4];
    #pragma unroll
    for (int mi = 0; mi < 2; mi++)
        #pragma unroll
        for (int nt = 0; nt < 8; nt++)
            #pragma unroll
            for (int r = 0; r < 4; r++) acc[mi][nt][r] = 0.f;

    const uint4* ebase = g_ebf + (size_t)z * 16 * 4096;
    auto issueB = [&](int c) {
        const uint4* src = ebase + c * 4096;
        const uint32_t bb = sbase + (8192 + ((unsigned)c % 3) * 16384) * 4;
        #pragma unroll
        for (int i = 0; i < 8; i++) {
            int f = t + i * 512;
            CP16(bb + f * 16, src + f);
        }
        CP_COMMIT();
    };
    issueB(0);
    issueB(1);

    #pragma unroll 1
    for (int c = 0; c < 16; c++) {
        if (c == 15) CP_WAIT0(); else CP_WAIT1();
        __syncthreads();
        if (c + 2 < 16) issueB(c + 2);

        uint4 ah[2], al[2];
        #pragma unroll
        for (int mi = 0; mi < 2; mi++) {
            ah[mi] = ((const uint4*)sm)[(c * 2 + mi) * 32 + lane];
            al[mi] = ((const uint4*)(sm + 4096))[(c * 2 + mi) * 32 + lane];
        }
        const uint4* Bu = (const uint4*)(sm + 8192 + ((unsigned)c % 3) * 16384);
        #pragma unroll
        for (int nt = 0; nt < 8; nt++) {
            uint4 b = Bu[(warp * 8 + nt) * 32 + lane];
            uint32_t bh[2] = { b.x, b.y };
            uint32_t bl[2] = { b.z, b.w };
            #pragma unroll
            for (int mi = 0; mi < 2; mi++) {
                mma_bf16(acc[mi][nt], (const uint32_t*)&ah[mi], bh);
                mma_bf16(acc[mi][nt], (const uint32_t*)&ah[mi], bl);
                mma_bf16(acc[mi][nt], (const uint32_t*)&al[mi], bh);
            }
        }
    }

    // ---- scale + mask + per-lane row max (4 row-slots per lane) ----
    const int ne = g_ne[z];
    const int lr = lane >> 2;
    float rmax[4] = { -FLT_MAX, -FLT_MAX, -FLT_MAX, -FLT_MAX };
    #pragma unroll
    for (int mi = 0; mi < 2; mi++)
        #pragma unroll
        for (int nt = 0; nt < 8; nt++) {
            int colb = warp * 64 + nt * 8 + (lane & 3) * 2;
            float p0 = (colb >= ne) ? 1e9f : 0.f;
            float p1 = (colb + 1 >= ne) ? 1e9f : 0.f;
            acc[mi][nt][0] = acc[mi][nt][0] * 0.0625f - p0;
            acc[mi][nt][1] = acc[mi][nt][1] * 0.0625f - p1;
            acc[mi][nt][2] = acc[mi][nt][2] * 0.0625f - p0;
            acc[mi][nt][3] = acc[mi][nt][3] * 0.0625f - p1;
            rmax[2 * mi]     = fmaxf(rmax[2 * mi],     fmaxf(acc[mi][nt][0], acc[mi][nt][1]));
            rmax[2 * mi + 1] = fmaxf(rmax[2 * mi + 1], fmaxf(acc[mi][nt][2], acc[mi][nt][3]));
        }
    #pragma unroll
    for (int j = 0; j < 4; j++) {
        rmax[j] = fmaxf(rmax[j], __shfl_xor_sync(0xffffffffu, rmax[j], 1));
        rmax[j] = fmaxf(rmax[j], __shfl_xor_sync(0xffffffffu, rmax[j], 2));
    }

    __syncthreads();                       // B stage 0 now dead; reuse as scratch
    float* pmax = (float*)(sm + 8192);     // [32 rows][16 warps]
    float* psum = pmax + 512;
    if ((lane & 3) == 0) {
        #pragma unroll
        for (int j = 0; j < 4; j++) pmax[(lr + j * 8) * 16 + warp] = rmax[j];
    }
    __syncthreads();
    float rm[4];
    #pragma unroll
    for (int j = 0; j < 4; j++) {
        float m = pmax[(lr + j * 8) * 16];
        #pragma unroll
        for (int w = 1; w < 16; w++) m = fmaxf(m, pmax[(lr + j * 8) * 16 + w]);
        rm[j] = m;
    }

    float rs[4] = { 0.f, 0.f, 0.f, 0.f };
    #pragma unroll
    for (int mi = 0; mi < 2; mi++)
        #pragma unroll
        for (int nt = 0; nt < 8; nt++) {
            acc[mi][nt][0] = __expf(acc[mi][nt][0] - rm[2 * mi]);
            acc[mi][nt][1] = __expf(acc[mi][nt][1] - rm[2 * mi]);
            acc[mi][nt][2] = __expf(acc[mi][nt][2] - rm[2 * mi + 1]);
            acc[mi][nt][3] = __expf(acc[mi][nt][3] - rm[2 * mi + 1]);
            rs[2 * mi]     += acc[mi][nt][0] + acc[mi][nt][1];
            rs[2 * mi + 1] += acc[mi][nt][2] + acc[mi][nt][3];
        }
    #pragma unroll
    for (int j = 0; j < 4; j++) {
        rs[j] += __shfl_xor_sync(0xffffffffu, rs[j], 1);
        rs[j] += __shfl_xor_sync(0xffffffffu, rs[j], 2);
    }
    if ((lane & 3) == 0) {
        #pragma unroll
        for (int j = 0; j < 4; j++) psum[(lr + j * 8) * 16 + warp] = rs[j];
    }
    __syncthreads();
    float inv[4];
    #pragma unroll
    for (int j = 0; j < 4; j++) {
        float s = 0.f;
        #pragma unroll
        for (int w = 0; w < 16; w++) s += psum[(lr + j * 8) * 16 + w];
        inv[j] = 1.f / s;
    }

    // ---- normalize + store ----
    #pragma unroll
    for (int mi = 0; mi < 2; mi++) {
        float* r0 = Ow + (size_t)(m0 + mi * 16 + lr) * ENUM;
        float* r1 = Ow + (size_t)(m0 + mi * 16 + lr + 8) * ENUM;
        #pragma unroll
        for (int nt = 0; nt < 8; nt++) {
            int colb = warp * 64 + nt * 8 + (lane & 3) * 2;
            *(float2*)(r0 + colb) =
                make_float2(acc[mi][nt][0] * inv[2 * mi], acc[mi][nt][1] * inv[2 * mi]);
            *(float2*)(r1 + colb) =
                make_float2(acc[mi][nt][2] * inv[2 * mi + 1], acc[mi][nt][3] * inv[2 * mi + 1]);
        }
    }
}

// ---------------------------------------------------------------------------
extern "C" void kernel_launch(void* const* d_in, const int* in_sizes, int n_in,
                              void* d_out, int out_size) {
    const float* ufeat = (const float*)d_in[0];   // [64,1024,512]
    const float* efeat = (const float*)d_in[1];   // [64,1024,256]
    const int*   neptr = (const int*)d_in[2];     // [64] int32 or int64
    const float* v     = (const float*)d_in[3];   // [256,512]
    const float* g     = (const float*)d_in[4];   // scalar
    const float* bias  = (const float*)d_in[5];   // [256]
    float* out = (float*)d_out;                   // [64,1024,1024]

    cudaFuncSetAttribute(proj_gemm, cudaFuncAttributeMaxDynamicSharedMemorySize, PSMEM_BYTES);
    cudaFuncSetAttribute(logit_softmax, cudaFuncAttributeMaxDynamicSharedMemorySize, FSMEM_BYTES);

    prep_partial<<<32, 1024>>>(v);
    prep_final<<<1, 32>>>(g, neptr);

    uconv<<<16384, 256>>>(ufeat);
    vconv<<<128, 256>>>(v);
    econv<<<16384, 256>>>(efeat);

    // proj: M=65536 (512 m-tiles), N=256 (2 n-tiles), K=512
    proj_gemm<<<dim3(2, 512), 256, PSMEM_BYTES>>>(bias);

    // fused logits + mask + softmax
    logit_softmax<<<dim3(UNUM / 32, BATCH), 512, FSMEM_BYTES>>>(out);
}

// round 8
// speedup vs baseline: 1.1515x; 1.0229x over previous
#include <cuda_runtime.h>
#include <cstdint>
#include <cfloat>

#define BATCH 64
#define UNUM  1024
#define ENUM  1024
#define UFD   512
#define EFD   256

__device__ float g_scale;
__device__ float g_part[32];
__device__ int   g_ne[BATCH];
__device__ uint4 g_ebf[(size_t)BATCH * 16 * 128 * 32];   // efeat B-frags (67MB)
__device__ uint4 g_ubf[(size_t)4096 * 32 * 32 * 2];      // ufeat A-frags hi/lo
__device__ uint4 g_vbf[(size_t)32 * 32 * 32];            // v B-frags
__device__ uint4 g_pbf[(size_t)4096 * 1024];             // proj A-frags: [m16][hi/lo 512][c*32+lane]

// ---------------------------------------------------------------------------
// helpers
// ---------------------------------------------------------------------------
__device__ __forceinline__ uint32_t packbf(float x0, float x1) {
    uint32_t r;
    asm("cvt.rn.bf16x2.f32 %0, %1, %2;" : "=r"(r) : "f"(x1), "f"(x0));
    return r;
}
__device__ __forceinline__ uint32_t lopack(uint32_t h, float x0, float x1) {
    float l0 = x0 - __uint_as_float(h << 16);
    float l1 = x1 - __uint_as_float(h & 0xffff0000u);
    return packbf(l0, l1);
}
__device__ __forceinline__ void mma_bf16(float* d, const uint32_t* a, const uint32_t* b) {
    asm volatile(
        "mma.sync.aligned.m16n8k16.row.col.f32.bf16.bf16.f32 "
        "{%0,%1,%2,%3}, {%4,%5,%6,%7}, {%8,%9}, {%0,%1,%2,%3};"
        : "+f"(d[0]), "+f"(d[1]), "+f"(d[2]), "+f"(d[3])
        : "r"(a[0]), "r"(a[1]), "r"(a[2]), "r"(a[3]), "r"(b[0]), "r"(b[1]));
}
__device__ __forceinline__ uint32_t smem_u32(const void* p) {
    uint32_t a;
    asm("{ .reg .u64 t; cvta.to.shared.u64 t, %1; cvt.u32.u64 %0, t; }" : "=r"(a) : "l"(p));
    return a;
}
#define CP16(dst, src) \
    asm volatile("cp.async.cg.shared.global [%0], [%1], 16;" :: "r"(dst), "l"(src) : "memory")
#define CP_COMMIT() asm volatile("cp.async.commit_group;" ::: "memory")
#define CP_WAIT1()  asm volatile("cp.async.wait_group 1;" ::: "memory")
#define CP_WAIT0()  asm volatile("cp.async.wait_group 0;" ::: "memory")

// ---------------------------------------------------------------------------
// prep: ||v||^2 partials + finalize + ne decode
// ---------------------------------------------------------------------------
__global__ __launch_bounds__(1024) void prep_partial(const float* __restrict__ v) {
    __shared__ float wsum[32];
    int tid = threadIdx.x, b = blockIdx.x;
    float s = 0.f;
    #pragma unroll
    for (int i = 0; i < 4; i++) {
        float x = v[b * 4096 + i * 1024 + tid];
        s += x * x;
    }
    #pragma unroll
    for (int o = 16; o; o >>= 1) s += __shfl_xor_sync(0xffffffffu, s, o);
    if ((tid & 31) == 0) wsum[tid >> 5] = s;
    __syncthreads();
    if (tid == 0) {
        float tot = 0.f;
        #pragma unroll
        for (int w = 0; w < 32; w++) tot += wsum[w];
        g_part[b] = tot;
    }
}
__global__ void prep_final(const float* __restrict__ g, const int* __restrict__ ne32) {
    if (threadIdx.x == 0) {
        float tot = 0.f;
        #pragma unroll
        for (int i = 0; i < 32; i++) tot += g_part[i];
        g_scale = g[0] / sqrtf(tot);
        bool is64 = true;
        for (int i = 0; i < 32; i++)
            if (ne32[2 * i + 1] != 0) { is64 = false; break; }
        for (int i = 0; i < BATCH; i++) g_ne[i] = is64 ? ne32[2 * i] : ne32[i];
    }
}

// ---------------------------------------------------------------------------
// econv: efeat -> B-fragment split bf16 (validated layout).
// ---------------------------------------------------------------------------
__global__ __launch_bounds__(256) void econv(const float* __restrict__ efeat) {
    uint32_t gid = blockIdx.x * 256 + threadIdx.x;
    int lane = gid & 31;
    int n8   = (gid >> 5) & 127;
    int c    = (gid >> 12) & 15;
    int z    = gid >> 16;
    int n    = n8 * 8 + (lane >> 2);
    int k0   = c * 16 + (lane & 3) * 2;
    const float* src = efeat + ((size_t)z * ENUM + n) * EFD;
    float2 f0 = *(const float2*)(src + k0);
    float2 f1 = *(const float2*)(src + k0 + 8);
    uint4 o;
    o.x = packbf(f0.x, f0.y);
    o.y = packbf(f1.x, f1.y);
    o.z = lopack(o.x, f0.x, f0.y);
    o.w = lopack(o.y, f1.x, f1.y);
    g_ebf[gid] = o;
}

// ---------------------------------------------------------------------------
// vconv: v [256][512] -> B-fragments [c(32)][n8(32)][lane]
// ---------------------------------------------------------------------------
__global__ __launch_bounds__(256) void vconv(const float* __restrict__ v) {
    uint32_t gid = blockIdx.x * 256 + threadIdx.x;   // 32768
    int lane = gid & 31;
    int n8   = (gid >> 5) & 31;
    int c    = gid >> 10;
    int n    = n8 * 8 + (lane >> 2);
    int k0   = c * 16 + (lane & 3) * 2;
    const float* src = v + (size_t)n * UFD;
    float2 f0 = *(const float2*)(src + k0);
    float2 f1 = *(const float2*)(src + k0 + 8);
    uint4 o;
    o.x = packbf(f0.x, f0.y);
    o.y = packbf(f1.x, f1.y);
    o.z = lopack(o.x, f0.x, f0.y);
    o.w = lopack(o.y, f1.x, f1.y);
    g_vbf[gid] = o;
}

// ---------------------------------------------------------------------------
// uconv: ufeat -> A-fragments (hi/lo interleaved pair per gid)
// ---------------------------------------------------------------------------
__global__ __launch_bounds__(256) void uconv(const float* __restrict__ uf) {
    uint32_t gid = blockIdx.x * 256 + threadIdx.x;   // 4,194,304
    int lane = gid & 31;
    int c    = (gid >> 5) & 31;
    int m16  = gid >> 10;
    int r    = m16 * 16 + (lane >> 2);
    int k0   = c * 16 + (lane & 3) * 2;
    const float* s0 = uf + (size_t)r * UFD;
    const float* s1 = uf + (size_t)(r + 8) * UFD;
    float2 a0 = *(const float2*)(s0 + k0);
    float2 a1 = *(const float2*)(s1 + k0);
    float2 a2 = *(const float2*)(s0 + k0 + 8);
    float2 a3 = *(const float2*)(s1 + k0 + 8);
    uint4 hi, lo;
    hi.x = packbf(a0.x, a0.y); hi.y = packbf(a1.x, a1.y);
    hi.z = packbf(a2.x, a2.y); hi.w = packbf(a3.x, a3.y);
    lo.x = lopack(hi.x, a0.x, a0.y); lo.y = lopack(hi.y, a1.x, a1.y);
    lo.z = lopack(hi.z, a2.x, a2.y); lo.w = lopack(hi.w, a3.x, a3.y);
    g_ubf[(size_t)gid * 2 + 0] = hi;
    g_ubf[(size_t)gid * 2 + 1] = lo;
}

// ---------------------------------------------------------------------------
// proj GEMM: relu(g_scale*(ufeat@v^T)+bias) -> g_pbf A-fragments (split bf16).
// Tile 128x128, 256 thr (2m x 4n warps, warp 64x32), 3-stage cp.async.
// ---------------------------------------------------------------------------
#define PSMEM_BYTES (3 * 1024 * 16)   // 48 KB

__global__ __launch_bounds__(256, 2) void proj_gemm(const float* __restrict__ bias) {
    extern __shared__ uint4 su[];
    const uint32_t sbase = smem_u32(su);
    const int t = threadIdx.x;
    const int warp = t >> 5, lane = t & 31;
    const int warpM = warp >> 2, warpN = warp & 3;
    const int m0 = blockIdx.y * 128, n0 = blockIdx.x * 128;
    const int m16base = blockIdx.y * 8;
    const int n8base = blockIdx.x * 16;

    float acc[4][4][4];
    #pragma unroll
    for (int i = 0; i < 4; i++)
        #pragma unroll
        for (int j = 0; j < 4; j++)
            #pragma unroll
            for (int r = 0; r < 4; r++) acc[i][j][r] = 0.f;

    constexpr int NCH = UFD / 16;   // 32

    auto issue = [&](int c) {
        const int s = ((unsigned)c) % 3;
        const uint32_t stb = sbase + s * 16384;
        #pragma unroll
        for (int i = 0; i < 2; i++) {          // A: 512 uint4
            int f = t + i * 256;
            int h = f >> 8, m16l = (f >> 5) & 7, ln = f & 31;
            const uint4* src = g_ubf + ((size_t)((m16base + m16l) * 32 + c) * 32 + ln) * 2 + h;
            CP16(stb + f * 16, src);
        }
        #pragma unroll
        for (int i = 0; i < 2; i++) {          // B: 512 uint4
            int f = t + i * 256;
            int n8l = f >> 5, ln = f & 31;
            const uint4* src = g_vbf + (size_t)(c * 32 + n8base + n8l) * 32 + ln;
            CP16(stb + (512 + f) * 16, src);
        }
        CP_COMMIT();
    };

    issue(0);
    issue(1);
    #pragma unroll 1
    for (int c = 0; c < NCH; c++) {
        if (c == NCH - 1) CP_WAIT0(); else CP_WAIT1();
        __syncthreads();
        if (c + 2 < NCH) issue(c + 2);

        const uint4* st = su + ((unsigned)c % 3) * 1024;
        uint4 ah[4], al[4], bb[4];
        #pragma unroll
        for (int mt = 0; mt < 4; mt++) {
            int idx = (warpM * 4 + mt) * 32 + lane;
            ah[mt] = st[idx];
            al[mt] = st[256 + idx];
        }
        #pragma unroll
        for (int nt = 0; nt < 4; nt++)
            bb[nt] = st[512 + (warpN * 4 + nt) * 32 + lane];
        #pragma unroll
        for (int mt = 0; mt < 4; mt++)
            #pragma unroll
            for (int nt = 0; nt < 4; nt++) {
                uint32_t bh[2] = { bb[nt].x, bb[nt].y };
                uint32_t bl[2] = { bb[nt].z, bb[nt].w };
                mma_bf16(acc[mt][nt], (const uint32_t*)&ah[mt], bh);
                mma_bf16(acc[mt][nt], (const uint32_t*)&ah[mt], bl);
                mma_bf16(acc[mt][nt], (const uint32_t*)&al[mt], bh);
            }
    }

    // ---- epilogue: scale+bias+relu, pack straight into A-fragment form ----
    // thread's acc[mt][2j] (+[2j+1]) == one fused-A fragment uint4 at its lane.
    const int cb0 = n0 + warpN * 32 + (lane & 3) * 2;
    const float s = g_scale;
    #pragma unroll
    for (int mt = 0; mt < 4; mt++) {
        const int m16g = m16base + warpM * 4 + mt;
        #pragma unroll
        for (int j = 0; j < 2; j++) {
            const int cglob = (n0 >> 4) + warpN * 2 + j;   // chunk 0..15
            float v0[4], v1[4];
            #pragma unroll
            for (int r = 0; r < 4; r++) {
                int col = cb0 + 2 * j * 8 + (r & 1);
                v0[r] = fmaxf(fmaf(s, acc[mt][2 * j][r], bias[col]), 0.f);
                v1[r] = fmaxf(fmaf(s, acc[mt][2 * j + 1][r], bias[col + 8]), 0.f);
            }
            uint4 hi, lo;
            hi.x = packbf(v0[0], v0[1]); hi.y = packbf(v0[2], v0[3]);
            hi.z = packbf(v1[0], v1[1]); hi.w = packbf(v1[2], v1[3]);
            lo.x = lopack(hi.x, v0[0], v0[1]); lo.y = lopack(hi.y, v0[2], v0[3]);
            lo.z = lopack(hi.z, v1[0], v1[1]); lo.w = lopack(hi.w, v1[2], v1[3]);
            uint4* dst = g_pbf + (size_t)m16g * 1024 + cglob * 32 + lane;
            dst[0]   = hi;     // hi block [0,512)
            dst[512] = lo;     // lo block [512,1024)
        }
    }
}

// ---------------------------------------------------------------------------
// Fused logit GEMM + mask + softmax.
// CTA M=32, N=1024, 512 thr = 16 warps (1m x 16n), warp tile 32x64.
// A-fragments cp.async'd from g_pbf (2048 uint4, pre-made by proj_gemm).
// B streamed from g_ebf, 3-stage. Softmax scratch reuses B stage 0.
// SMEM words: A [0,8192) = per-m16 {hi 512, lo 512} uint4 blocks
//             B stages [8192 + s*16384)
// ---------------------------------------------------------------------------
#define FSMEM_BYTES ((8192 + 3 * 16384) * 4)   // 229376

__global__ __launch_bounds__(512, 1) void logit_softmax(float* __restrict__ out) {
    extern __shared__ uint32_t sm[];
    const uint32_t sbase = smem_u32(sm);
    const int t = threadIdx.x;
    const int warp = t >> 5, lane = t & 31;
    const int z = blockIdx.y, m0 = blockIdx.x * 32;
    float* Ow = out + (size_t)z * UNUM * ENUM;

    // ---- A: cp.async pre-made fragments (contiguous 2048 uint4) ----
    {
        const uint4* asrc = g_pbf + (size_t)(z * 64 + blockIdx.x * 2) * 1024;
        #pragma unroll
        for (int i = 0; i < 4; i++) {
            int f = t + i * 512;
            CP16(sbase + f * 16, asrc + f);
        }
        CP_COMMIT();
    }

    float acc[2][8][4];
    #pragma unroll
    for (int mi = 0; mi < 2; mi++)
        #pragma unroll
        for (int nt = 0; nt < 8; nt++)
            #pragma unroll
            for (int r = 0; r < 4; r++) acc[mi][nt][r] = 0.f;

    const uint4* ebase = g_ebf + (size_t)z * 16 * 4096;
    auto issueB = [&](int c) {
        const uint4* src = ebase + c * 4096;
        const uint32_t bb = sbase + (8192 + ((unsigned)c % 3) * 16384) * 4;
        #pragma unroll
        for (int i = 0; i < 8; i++) {
            int f = t + i * 512;
            CP16(bb + f * 16, src + f);
        }
        CP_COMMIT();
    };
    issueB(0);
    issueB(1);

    const uint4* sA4 = (const uint4*)sm;

    #pragma unroll 1
    for (int c = 0; c < 16; c++) {
        if (c == 15) CP_WAIT0(); else CP_WAIT1();
        __syncthreads();
        if (c + 2 < 16) issueB(c + 2);

        uint4 ah[2], al[2];
        #pragma unroll
        for (int mi = 0; mi < 2; mi++) {
            ah[mi] = sA4[mi * 1024 + c * 32 + lane];
            al[mi] = sA4[mi * 1024 + 512 + c * 32 + lane];
        }
        const uint4* Bu = (const uint4*)(sm + 8192 + ((unsigned)c % 3) * 16384);
        #pragma unroll
        for (int nt = 0; nt < 8; nt++) {
            uint4 b = Bu[(warp * 8 + nt) * 32 + lane];
            uint32_t bh[2] = { b.x, b.y };
            uint32_t bl[2] = { b.z, b.w };
            #pragma unroll
            for (int mi = 0; mi < 2; mi++) {
                mma_bf16(acc[mi][nt], (const uint32_t*)&ah[mi], bh);
                mma_bf16(acc[mi][nt], (const uint32_t*)&ah[mi], bl);
                mma_bf16(acc[mi][nt], (const uint32_t*)&al[mi], bh);
            }
        }
    }

    // ---- scale + mask + per-lane row max ----
    const int ne = g_ne[z];
    const int lr = lane >> 2;
    float rmax[4] = { -FLT_MAX, -FLT_MAX, -FLT_MAX, -FLT_MAX };
    #pragma unroll
    for (int mi = 0; mi < 2; mi++)
        #pragma unroll
        for (int nt = 0; nt < 8; nt++) {
            int colb = warp * 64 + nt * 8 + (lane & 3) * 2;
            float p0 = (colb >= ne) ? 1e9f : 0.f;
            float p1 = (colb + 1 >= ne) ? 1e9f : 0.f;
            acc[mi][nt][0] = acc[mi][nt][0] * 0.0625f - p0;
            acc[mi][nt][1] = acc[mi][nt][1] * 0.0625f - p1;
            acc[mi][nt][2] = acc[mi][nt][2] * 0.0625f - p0;
            acc[mi][nt][3] = acc[mi][nt][3] * 0.0625f - p1;
            rmax[2 * mi]     = fmaxf(rmax[2 * mi],     fmaxf(acc[mi][nt][0], acc[mi][nt][1]));
            rmax[2 * mi + 1] = fmaxf(rmax[2 * mi + 1], fmaxf(acc[mi][nt][2], acc[mi][nt][3]));
        }
    #pragma unroll
    for (int j = 0; j < 4; j++) {
        rmax[j] = fmaxf(rmax[j], __shfl_xor_sync(0xffffffffu, rmax[j], 1));
        rmax[j] = fmaxf(rmax[j], __shfl_xor_sync(0xffffffffu, rmax[j], 2));
    }

    __syncthreads();                       // B stage 0 dead; reuse as scratch
    float* pmax = (float*)(sm + 8192);     // [32 rows][16 warps]
    float* psum = pmax + 512;
    if ((lane & 3) == 0) {
        #pragma unroll
        for (int j = 0; j < 4; j++) pmax[(lr + j * 8) * 16 + warp] = rmax[j];
    }
    __syncthreads();
    float rm[4];
    #pragma unroll
    for (int j = 0; j < 4; j++) {
        float m = pmax[(lr + j * 8) * 16];
        #pragma unroll
        for (int w = 1; w < 16; w++) m = fmaxf(m, pmax[(lr + j * 8) * 16 + w]);
        rm[j] = m;
    }

    float rs[4] = { 0.f, 0.f, 0.f, 0.f };
    #pragma unroll
    for (int mi = 0; mi < 2; mi++)
        #pragma unroll
        for (int nt = 0; nt < 8; nt++) {
            acc[mi][nt][0] = __expf(acc[mi][nt][0] - rm[2 * mi]);
            acc[mi][nt][1] = __expf(acc[mi][nt][1] - rm[2 * mi]);
            acc[mi][nt][2] = __expf(acc[mi][nt][2] - rm[2 * mi + 1]);
            acc[mi][nt][3] = __expf(acc[mi][nt][3] - rm[2 * mi + 1]);
            rs[2 * mi]     += acc[mi][nt][0] + acc[mi][nt][1];
            rs[2 * mi + 1] += acc[mi][nt][2] + acc[mi][nt][3];
        }
    #pragma unroll
    for (int j = 0; j < 4; j++) {
        rs[j] += __shfl_xor_sync(0xffffffffu, rs[j], 1);
        rs[j] += __shfl_xor_sync(0xffffffffu, rs[j], 2);
    }
    if ((lane & 3) == 0) {
        #pragma unroll
        for (int j = 0; j < 4; j++) psum[(lr + j * 8) * 16 + warp] = rs[j];
    }
    __syncthreads();
    float inv[4];
    #pragma unroll
    for (int j = 0; j < 4; j++) {
        float s = 0.f;
        #pragma unroll
        for (int w = 0; w < 16; w++) s += psum[(lr + j * 8) * 16 + w];
        inv[j] = 1.f / s;
    }

    // ---- normalize + store ----
    #pragma unroll
    for (int mi = 0; mi < 2; mi++) {
        float* r0 = Ow + (size_t)(m0 + mi * 16 + lr) * ENUM;
        float* r1 = Ow + (size_t)(m0 + mi * 16 + lr + 8) * ENUM;
        #pragma unroll
        for (int nt = 0; nt < 8; nt++) {
            int colb = warp * 64 + nt * 8 + (lane & 3) * 2;
            *(float2*)(r0 + colb) =
                make_float2(acc[mi][nt][0] * inv[2 * mi], acc[mi][nt][1] * inv[2 * mi]);
            *(float2*)(r1 + colb) =
                make_float2(acc[mi][nt][2] * inv[2 * mi + 1], acc[mi][nt][3] * inv[2 * mi + 1]);
        }
    }
}

// ---------------------------------------------------------------------------
extern "C" void kernel_launch(void* const* d_in, const int* in_sizes, int n_in,
                              void* d_out, int out_size) {
    const float* ufeat = (const float*)d_in[0];   // [64,1024,512]
    const float* efeat = (const float*)d_in[1];   // [64,1024,256]
    const int*   neptr = (const int*)d_in[2];     // [64] int32 or int64
    const float* v     = (const float*)d_in[3];   // [256,512]
    const float* g     = (const float*)d_in[4];   // scalar
    const float* bias  = (const float*)d_in[5];   // [256]
    float* out = (float*)d_out;                   // [64,1024,1024]

    cudaFuncSetAttribute(proj_gemm, cudaFuncAttributeMaxDynamicSharedMemorySize, PSMEM_BYTES);
    cudaFuncSetAttribute(logit_softmax, cudaFuncAttributeMaxDynamicSharedMemorySize, FSMEM_BYTES);

    prep_partial<<<32, 1024>>>(v);
    prep_final<<<1, 32>>>(g, neptr);

    uconv<<<16384, 256>>>(ufeat);
    vconv<<<128, 256>>>(v);
    econv<<<16384, 256>>>(efeat);

    // proj: M=65536 (512 m-tiles), N=256 (2 n-tiles), K=512 -> g_pbf frags
    proj_gemm<<<dim3(2, 512), 256, PSMEM_BYTES>>>(bias);

    // fused logits + mask + softmax
    logit_softmax<<<dim3(UNUM / 32, BATCH), 512, FSMEM_BYTES>>>(out);
}

// round 9
// speedup vs baseline: 1.6628x; 1.4440x over previous
#include <cuda_runtime.h>
#include <cstdint>
#include <cfloat>

#define BATCH 64
#define UNUM  1024
#define ENUM  1024
#define UFD   512
#define EFD   256

__device__ float g_scale;
__device__ float g_part[32];
__device__ int   g_ne[BATCH];
__device__ uint2 g_ebf2[(size_t)BATCH * 16 * 128 * 32];  // efeat B-frags, fp16 hi only
__device__ uint4 g_ubf[(size_t)4096 * 32 * 32 * 2];      // ufeat A-frags fp16 hi/lo
__device__ uint4 g_vbf[(size_t)32 * 32 * 32];            // v B-frags fp16 hi/lo
__device__ uint4 g_pbf[(size_t)4096 * 512];              // proj A-frags, fp16 hi only

// ---------------------------------------------------------------------------
// helpers (fp16 split precision)
// ---------------------------------------------------------------------------
__device__ __forceinline__ uint32_t packh(float x0, float x1) {
    uint32_t r;   // {hi16: fp16(x1), lo16: fp16(x0)}  (x0 = even k)
    asm("cvt.rn.f16x2.f32 %0, %1, %2;" : "=r"(r) : "f"(x1), "f"(x0));
    return r;
}
__device__ __forceinline__ uint32_t lopackh(uint32_t h, float x0, float x1) {
    float h0, h1;
    asm("{ .reg .b16 a, b; mov.b32 {a, b}, %2; cvt.f32.f16 %0, a; cvt.f32.f16 %1, b; }"
        : "=f"(h0), "=f"(h1) : "r"(h));
    return packh(x0 - h0, x1 - h1);
}
__device__ __forceinline__ void mma_f16(float* d, const uint32_t* a, const uint32_t* b) {
    asm volatile(
        "mma.sync.aligned.m16n8k16.row.col.f32.f16.f16.f32 "
        "{%0,%1,%2,%3}, {%4,%5,%6,%7}, {%8,%9}, {%0,%1,%2,%3};"
        : "+f"(d[0]), "+f"(d[1]), "+f"(d[2]), "+f"(d[3])
        : "r"(a[0]), "r"(a[1]), "r"(a[2]), "r"(a[3]), "r"(b[0]), "r"(b[1]));
}
__device__ __forceinline__ uint32_t smem_u32(const void* p) {
    uint32_t a;
    asm("{ .reg .u64 t; cvta.to.shared.u64 t, %1; cvt.u32.u64 %0, t; }" : "=r"(a) : "l"(p));
    return a;
}
#define CP16(dst, src) \
    asm volatile("cp.async.cg.shared.global [%0], [%1], 16;" :: "r"(dst), "l"(src) : "memory")
#define CP_COMMIT() asm volatile("cp.async.commit_group;" ::: "memory")
#define CP_WAIT1()  asm volatile("cp.async.wait_group 1;" ::: "memory")
#define CP_WAIT0()  asm volatile("cp.async.wait_group 0;" ::: "memory")

// ---------------------------------------------------------------------------
// prep_partial: ||v||^2 partials (deterministic slots)
// ---------------------------------------------------------------------------
__global__ __launch_bounds__(1024) void prep_partial(const float* __restrict__ v) {
    __shared__ float wsum[32];
    int tid = threadIdx.x, b = blockIdx.x;
    float s = 0.f;
    #pragma unroll
    for (int i = 0; i < 4; i++) {
        float x = v[b * 4096 + i * 1024 + tid];
        s += x * x;
    }
    #pragma unroll
    for (int o = 16; o; o >>= 1) s += __shfl_xor_sync(0xffffffffu, s, o);
    if ((tid & 31) == 0) wsum[tid >> 5] = s;
    __syncthreads();
    if (tid == 0) {
        float tot = 0.f;
        #pragma unroll
        for (int w = 0; w < 32; w++) tot += wsum[w];
        g_part[b] = tot;
    }
}

// ---------------------------------------------------------------------------
// conv_all: one launch doing finalize + uconv + vconv + econv.
// blocks [0,16384): ufeat -> A-frags hi/lo
// blocks [16384,16512): v -> B-frags hi/lo
// blocks [16512,32896): efeat -> B-frags hi only (uint2)
// block 0 thread 0 additionally finalizes g_scale / g_ne.
// ---------------------------------------------------------------------------
__global__ __launch_bounds__(256) void conv_all(const float* __restrict__ uf,
                                                const float* __restrict__ v,
                                                const float* __restrict__ ef,
                                                const float* __restrict__ g,
                                                const int* __restrict__ ne32) {
    const uint32_t b = blockIdx.x;
    const int t = threadIdx.x;
    if (b == 0 && t == 0) {
        float tot = 0.f;
        #pragma unroll
        for (int i = 0; i < 32; i++) tot += g_part[i];
        g_scale = g[0] / sqrtf(tot);
        bool is64 = true;
        for (int i = 0; i < 32; i++)
            if (ne32[2 * i + 1] != 0) { is64 = false; break; }
        for (int i = 0; i < BATCH; i++) g_ne[i] = is64 ? ne32[2 * i] : ne32[i];
    }

    if (b < 16384) {                    // ---- uconv ----
        uint32_t gid = b * 256 + t;
        int lane = gid & 31;
        int c    = (gid >> 5) & 31;
        int m16  = gid >> 10;
        int r    = m16 * 16 + (lane >> 2);
        int k0   = c * 16 + (lane & 3) * 2;
        const float* s0 = uf + (size_t)r * UFD;
        const float* s1 = uf + (size_t)(r + 8) * UFD;
        float2 a0 = *(const float2*)(s0 + k0);
        float2 a1 = *(const float2*)(s1 + k0);
        float2 a2 = *(const float2*)(s0 + k0 + 8);
        float2 a3 = *(const float2*)(s1 + k0 + 8);
        uint4 hi, lo;
        hi.x = packh(a0.x, a0.y); hi.y = packh(a1.x, a1.y);
        hi.z = packh(a2.x, a2.y); hi.w = packh(a3.x, a3.y);
        lo.x = lopackh(hi.x, a0.x, a0.y); lo.y = lopackh(hi.y, a1.x, a1.y);
        lo.z = lopackh(hi.z, a2.x, a2.y); lo.w = lopackh(hi.w, a3.x, a3.y);
        g_ubf[(size_t)gid * 2 + 0] = hi;
        g_ubf[(size_t)gid * 2 + 1] = lo;
    } else if (b < 16512) {             // ---- vconv ----
        uint32_t gid = (b - 16384) * 256 + t;
        int lane = gid & 31;
        int n8   = (gid >> 5) & 31;
        int c    = gid >> 10;
        int n    = n8 * 8 + (lane >> 2);
        int k0   = c * 16 + (lane & 3) * 2;
        const float* src = v + (size_t)n * UFD;
        float2 f0 = *(const float2*)(src + k0);
        float2 f1 = *(const float2*)(src + k0 + 8);
        uint4 o;
        o.x = packh(f0.x, f0.y);
        o.y = packh(f1.x, f1.y);
        o.z = lopackh(o.x, f0.x, f0.y);
        o.w = lopackh(o.y, f1.x, f1.y);
        g_vbf[gid] = o;
    } else {                            // ---- econv (hi only) ----
        uint32_t gid = (b - 16512) * 256 + t;
        int lane = gid & 31;
        int n8   = (gid >> 5) & 127;
        int c    = (gid >> 12) & 15;
        int z    = gid >> 16;
        int n    = n8 * 8 + (lane >> 2);
        int k0   = c * 16 + (lane & 3) * 2;
        const float* src = ef + ((size_t)z * ENUM + n) * EFD;
        float2 f0 = *(const float2*)(src + k0);
        float2 f1 = *(const float2*)(src + k0 + 8);
        uint2 o;
        o.x = packh(f0.x, f0.y);
        o.y = packh(f1.x, f1.y);
        g_ebf2[gid] = o;
    }
}

// ---------------------------------------------------------------------------
// proj GEMM: relu(g_scale*(ufeat@v^T)+bias) -> g_pbf A-frags (fp16 hi only).
// fp16 3-MMA split (full precision). Tile 128x128, 256 thr, 3-stage cp.async.
// ---------------------------------------------------------------------------
#define PSMEM_BYTES (3 * 1024 * 16)   // 48 KB

__global__ __launch_bounds__(256, 2) void proj_gemm(const float* __restrict__ bias) {
    extern __shared__ uint4 su[];
    const uint32_t sbase = smem_u32(su);
    const int t = threadIdx.x;
    const int warp = t >> 5, lane = t & 31;
    const int warpM = warp >> 2, warpN = warp & 3;
    const int n0 = blockIdx.x * 128;
    const int m16base = blockIdx.y * 8;
    const int n8base = blockIdx.x * 16;

    float acc[4][4][4];
    #pragma unroll
    for (int i = 0; i < 4; i++)
        #pragma unroll
        for (int j = 0; j < 4; j++)
            #pragma unroll
            for (int r = 0; r < 4; r++) acc[i][j][r] = 0.f;

    constexpr int NCH = UFD / 16;   // 32

    auto issue = [&](int c) {
        const int s = ((unsigned)c) % 3;
        const uint32_t stb = sbase + s * 16384;
        #pragma unroll
        for (int i = 0; i < 2; i++) {          // A: 512 uint4
            int f = t + i * 256;
            int h = f >> 8, m16l = (f >> 5) & 7, ln = f & 31;
            const uint4* src = g_ubf + ((size_t)((m16base + m16l) * 32 + c) * 32 + ln) * 2 + h;
            CP16(stb + f * 16, src);
        }
        #pragma unroll
        for (int i = 0; i < 2; i++) {          // B: 512 uint4
            int f = t + i * 256;
            int n8l = f >> 5, ln = f & 31;
            const uint4* src = g_vbf + (size_t)(c * 32 + n8base + n8l) * 32 + ln;
            CP16(stb + (512 + f) * 16, src);
        }
        CP_COMMIT();
    };

    issue(0);
    issue(1);
    #pragma unroll 1
    for (int c = 0; c < NCH; c++) {
        if (c == NCH - 1) CP_WAIT0(); else CP_WAIT1();
        __syncthreads();
        if (c + 2 < NCH) issue(c + 2);

        const uint4* st = su + ((unsigned)c % 3) * 1024;
        uint4 ah[4], al[4], bb[4];
        #pragma unroll
        for (int mt = 0; mt < 4; mt++) {
            int idx = (warpM * 4 + mt) * 32 + lane;
            ah[mt] = st[idx];
            al[mt] = st[256 + idx];
        }
        #pragma unroll
        for (int nt = 0; nt < 4; nt++)
            bb[nt] = st[512 + (warpN * 4 + nt) * 32 + lane];
        #pragma unroll
        for (int mt = 0; mt < 4; mt++)
            #pragma unroll
            for (int nt = 0; nt < 4; nt++) {
                uint32_t bh[2] = { bb[nt].x, bb[nt].y };
                uint32_t bl[2] = { bb[nt].z, bb[nt].w };
                mma_f16(acc[mt][nt], (const uint32_t*)&ah[mt], bh);
                mma_f16(acc[mt][nt], (const uint32_t*)&ah[mt], bl);
                mma_f16(acc[mt][nt], (const uint32_t*)&al[mt], bh);
            }
    }

    // ---- epilogue: scale+bias+relu, pack into fp16-hi A-fragment form ----
    const int cb0 = n0 + warpN * 32 + (lane & 3) * 2;
    const float s = g_scale;
    #pragma unroll
    for (int mt = 0; mt < 4; mt++) {
        const int m16g = m16base + warpM * 4 + mt;
        #pragma unroll
        for (int j = 0; j < 2; j++) {
            const int cglob = (n0 >> 4) + warpN * 2 + j;   // chunk 0..15
            float v0[4], v1[4];
            #pragma unroll
            for (int r = 0; r < 4; r++) {
                int col = cb0 + 2 * j * 8 + (r & 1);
                v0[r] = fmaxf(fmaf(s, acc[mt][2 * j][r], bias[col]), 0.f);
                v1[r] = fmaxf(fmaf(s, acc[mt][2 * j + 1][r], bias[col + 8]), 0.f);
            }
            uint4 hi;
            hi.x = packh(v0[0], v0[1]); hi.y = packh(v0[2], v0[3]);
            hi.z = packh(v1[0], v1[1]); hi.w = packh(v1[2], v1[3]);
            g_pbf[(size_t)m16g * 512 + cglob * 32 + lane] = hi;
        }
    }
}

// ---------------------------------------------------------------------------
// Fused logit GEMM + mask + softmax.  PURE fp16: 1 MMA per (mi,nt,chunk).
// CTA M=32, N=1024, 512 thr (1m x 16n warps), warp tile 32x64.
// SMEM (uint4): A [0,1024)  B stage s at [1024 + s*2048)  (3 stages, 32KB each)
// ---------------------------------------------------------------------------
#define FSMEM_BYTES ((1024 + 3 * 2048) * 16)   // 114688

__global__ __launch_bounds__(512, 1) void logit_softmax(float* __restrict__ out) {
    extern __shared__ uint32_t sm[];
    const uint32_t sbase = smem_u32(sm);
    const int t = threadIdx.x;
    const int warp = t >> 5, lane = t & 31;
    const int z = blockIdx.y, m0 = blockIdx.x * 32;
    float* Ow = out + (size_t)z * UNUM * ENUM;

    // ---- A: cp.async pre-made hi fragments (1024 uint4 contiguous) ----
    {
        const uint4* asrc = g_pbf + (size_t)(z * 64 + blockIdx.x * 2) * 512;
        #pragma unroll
        for (int i = 0; i < 2; i++) {
            int f = t + i * 512;
            CP16(sbase + f * 16, asrc + f);
        }
        CP_COMMIT();
    }

    float acc[2][8][4];
    #pragma unroll
    for (int mi = 0; mi < 2; mi++)
        #pragma unroll
        for (int nt = 0; nt < 8; nt++)
            #pragma unroll
            for (int r = 0; r < 4; r++) acc[mi][nt][r] = 0.f;

    const uint4* ebase = (const uint4*)(g_ebf2 + (size_t)z * 16 * 4096);
    auto issueB = [&](int c) {
        const uint4* src = ebase + c * 2048;
        const uint32_t bb = sbase + (1024 + ((unsigned)c % 3) * 2048) * 16;
        #pragma unroll
        for (int i = 0; i < 4; i++) {
            int f = t + i * 512;
            CP16(bb + f * 16, src + f);
        }
        CP_COMMIT();
    };
    issueB(0);
    issueB(1);

    const uint4* sA4 = (const uint4*)sm;

    #pragma unroll 1
    for (int c = 0; c < 16; c++) {
        if (c == 15) CP_WAIT0(); else CP_WAIT1();
        __syncthreads();
        if (c + 2 < 16) issueB(c + 2);

        uint4 ah0 = sA4[c * 32 + lane];
        uint4 ah1 = sA4[512 + c * 32 + lane];
        const uint2* Bu = (const uint2*)(sA4 + 1024 + ((unsigned)c % 3) * 2048);
        #pragma unroll
        for (int nt = 0; nt < 8; nt++) {
            uint2 b = Bu[(warp * 8 + nt) * 32 + lane];
            uint32_t br[2] = { b.x, b.y };
            mma_f16(acc[0][nt], (const uint32_t*)&ah0, br);
            mma_f16(acc[1][nt], (const uint32_t*)&ah1, br);
        }
    }

    // ---- scale + mask + per-lane row max ----
    const int ne = g_ne[z];
    const int lr = lane >> 2;
    float rmax[4] = { -FLT_MAX, -FLT_MAX, -FLT_MAX, -FLT_MAX };
    #pragma unroll
    for (int mi = 0; mi < 2; mi++)
        #pragma unroll
        for (int nt = 0; nt < 8; nt++) {
            int colb = warp * 64 + nt * 8 + (lane & 3) * 2;
            float p0 = (colb >= ne) ? 1e9f : 0.f;
            float p1 = (colb + 1 >= ne) ? 1e9f : 0.f;
            acc[mi][nt][0] = acc[mi][nt][0] * 0.0625f - p0;
            acc[mi][nt][1] = acc[mi][nt][1] * 0.0625f - p1;
            acc[mi][nt][2] = acc[mi][nt][2] * 0.0625f - p0;
            acc[mi][nt][3] = acc[mi][nt][3] * 0.0625f - p1;
            rmax[2 * mi]     = fmaxf(rmax[2 * mi],     fmaxf(acc[mi][nt][0], acc[mi][nt][1]));
            rmax[2 * mi + 1] = fmaxf(rmax[2 * mi + 1], fmaxf(acc[mi][nt][2], acc[mi][nt][3]));
        }
    #pragma unroll
    for (int j = 0; j < 4; j++) {
        rmax[j] = fmaxf(rmax[j], __shfl_xor_sync(0xffffffffu, rmax[j], 1));
        rmax[j] = fmaxf(rmax[j], __shfl_xor_sync(0xffffffffu, rmax[j], 2));
    }

    __syncthreads();                        // B stage 0 dead; reuse as scratch
    float* pmax = (float*)(sm + 4096);      // [32 rows][16 warps]
    float* psum = pmax + 512;
    if ((lane & 3) == 0) {
        #pragma unroll
        for (int j = 0; j < 4; j++) pmax[(lr + j * 8) * 16 + warp] = rmax[j];
    }
    __syncthreads();
    float rm[4];
    #pragma unroll
    for (int j = 0; j < 4; j++) {
        float m = pmax[(lr + j * 8) * 16];
        #pragma unroll
        for (int w = 1; w < 16; w++) m = fmaxf(m, pmax[(lr + j * 8) * 16 + w]);
        rm[j] = m;
    }

    float rs[4] = { 0.f, 0.f, 0.f, 0.f };
    #pragma unroll
    for (int mi = 0; mi < 2; mi++)
        #pragma unroll
        for (int nt = 0; nt < 8; nt++) {
            acc[mi][nt][0] = __expf(acc[mi][nt][0] - rm[2 * mi]);
            acc[mi][nt][1] = __expf(acc[mi][nt][1] - rm[2 * mi]);
            acc[mi][nt][2] = __expf(acc[mi][nt][2] - rm[2 * mi + 1]);
            acc[mi][nt][3] = __expf(acc[mi][nt][3] - rm[2 * mi + 1]);
            rs[2 * mi]     += acc[mi][nt][0] + acc[mi][nt][1];
            rs[2 * mi + 1] += acc[mi][nt][2] + acc[mi][nt][3];
        }
    #pragma unroll
    for (int j = 0; j < 4; j++) {
        rs[j] += __shfl_xor_sync(0xffffffffu, rs[j], 1);
        rs[j] += __shfl_xor_sync(0xffffffffu, rs[j], 2);
    }
    if ((lane & 3) == 0) {
        #pragma unroll
        for (int j = 0; j < 4; j++) psum[(lr + j * 8) * 16 + warp] = rs[j];
    }
    __syncthreads();
    float inv[4];
    #pragma unroll
    for (int j = 0; j < 4; j++) {
        float s = 0.f;
        #pragma unroll
        for (int w = 0; w < 16; w++) s += psum[(lr + j * 8) * 16 + w];
        inv[j] = 1.f / s;
    }

    // ---- normalize + store ----
    #pragma unroll
    for (int mi = 0; mi < 2; mi++) {
        float* r0 = Ow + (size_t)(m0 + mi * 16 + lr) * ENUM;
        float* r1 = Ow + (size_t)(m0 + mi * 16 + lr + 8) * ENUM;
        #pragma unroll
        for (int nt = 0; nt < 8; nt++) {
            int colb = warp * 64 + nt * 8 + (lane & 3) * 2;
            *(float2*)(r0 + colb) =
                make_float2(acc[mi][nt][0] * inv[2 * mi], acc[mi][nt][1] * inv[2 * mi]);
            *(float2*)(r1 + colb) =
                make_float2(acc[mi][nt][2] * inv[2 * mi + 1], acc[mi][nt][3] * inv[2 * mi + 1]);
        }
    }
}

// ---------------------------------------------------------------------------
extern "C" void kernel_launch(void* const* d_in, const int* in_sizes, int n_in,
                              void* d_out, int out_size) {
    const float* ufeat = (const float*)d_in[0];   // [64,1024,512]
    const float* efeat = (const float*)d_in[1];   // [64,1024,256]
    const int*   neptr = (const int*)d_in[2];     // [64] int32 or int64
    const float* v     = (const float*)d_in[3];   // [256,512]
    const float* g     = (const float*)d_in[4];   // scalar
    const float* bias  = (const float*)d_in[5];   // [256]
    float* out = (float*)d_out;                   // [64,1024,1024]

    cudaFuncSetAttribute(proj_gemm, cudaFuncAttributeMaxDynamicSharedMemorySize, PSMEM_BYTES);
    cudaFuncSetAttribute(logit_softmax, cudaFuncAttributeMaxDynamicSharedMemorySize, FSMEM_BYTES);

    prep_partial<<<32, 1024>>>(v);                               // launch 0
    conv_all<<<32896, 256>>>(ufeat, v, efeat, g, neptr);          // launch 1
    proj_gemm<<<dim3(2, 512), 256, PSMEM_BYTES>>>(bias);          // launch 2
    logit_softmax<<<dim3(UNUM / 32, BATCH), 512, FSMEM_BYTES>>>(out);  // launch 3
}

// round 10
// speedup vs baseline: 2.1496x; 1.2927x over previous
#include <cuda_runtime.h>
#include <cstdint>
#include <cfloat>

#define BATCH 64
#define UNUM  1024
#define ENUM  1024
#define UFD   512
#define EFD   256

__device__ float g_scale;
__device__ float g_part[32];
__device__ int   g_ne[BATCH];
__device__ uint2 g_ebf2[(size_t)BATCH * 16 * 128 * 32];  // efeat B-frags fp16 hi
__device__ uint4 g_ubf2[(size_t)4096 * 32 * 32];         // ufeat A-frags fp16 hi
__device__ uint2 g_vbf2[(size_t)32 * 16 * 32 * 2];       // v B-frags fp16 hi ([c][n8][lane])
__device__ uint4 g_pbf[(size_t)4096 * 512];              // proj A-frags fp16 hi

// ---------------------------------------------------------------------------
// helpers
// ---------------------------------------------------------------------------
__device__ __forceinline__ uint32_t packh(float x0, float x1) {
    uint32_t r;   // {hi16: fp16(x1), lo16: fp16(x0)}
    asm("cvt.rn.f16x2.f32 %0, %1, %2;" : "=r"(r) : "f"(x1), "f"(x0));
    return r;
}
__device__ __forceinline__ void mma_f16(float* d, const uint32_t* a, const uint32_t* b) {
    asm volatile(
        "mma.sync.aligned.m16n8k16.row.col.f32.f16.f16.f32 "
        "{%0,%1,%2,%3}, {%4,%5,%6,%7}, {%8,%9}, {%0,%1,%2,%3};"
        : "+f"(d[0]), "+f"(d[1]), "+f"(d[2]), "+f"(d[3])
        : "r"(a[0]), "r"(a[1]), "r"(a[2]), "r"(a[3]), "r"(b[0]), "r"(b[1]));
}
__device__ __forceinline__ uint32_t smem_u32(const void* p) {
    uint32_t a;
    asm("{ .reg .u64 t; cvta.to.shared.u64 t, %1; cvt.u32.u64 %0, t; }" : "=r"(a) : "l"(p));
    return a;
}
#define CP16(dst, src) \
    asm volatile("cp.async.cg.shared.global [%0], [%1], 16;" :: "r"(dst), "l"(src) : "memory")
#define CP_COMMIT() asm volatile("cp.async.commit_group;" ::: "memory")
#define CP_WAIT1()  asm volatile("cp.async.wait_group 1;" ::: "memory")
#define CP_WAIT0()  asm volatile("cp.async.wait_group 0;" ::: "memory")

// ---------------------------------------------------------------------------
// prep_partial: ||v||^2 partials
// ---------------------------------------------------------------------------
__global__ __launch_bounds__(1024) void prep_partial(const float* __restrict__ v) {
    __shared__ float wsum[32];
    int tid = threadIdx.x, b = blockIdx.x;
    float s = 0.f;
    #pragma unroll
    for (int i = 0; i < 4; i++) {
        float x = v[b * 4096 + i * 1024 + tid];
        s += x * x;
    }
    #pragma unroll
    for (int o = 16; o; o >>= 1) s += __shfl_xor_sync(0xffffffffu, s, o);
    if ((tid & 31) == 0) wsum[tid >> 5] = s;
    __syncthreads();
    if (tid == 0) {
        float tot = 0.f;
        #pragma unroll
        for (int w = 0; w < 32; w++) tot += wsum[w];
        g_part[b] = tot;
    }
}

// ---------------------------------------------------------------------------
// conv_all: finalize + uconv(hi) + vconv(hi) + econv(hi), one launch.
// ---------------------------------------------------------------------------
__global__ __launch_bounds__(256) void conv_all(const float* __restrict__ uf,
                                                const float* __restrict__ v,
                                                const float* __restrict__ ef,
                                                const float* __restrict__ g,
                                                const int* __restrict__ ne32) {
    const uint32_t b = blockIdx.x;
    const int t = threadIdx.x;
    if (b == 0 && t == 0) {
        float tot = 0.f;
        #pragma unroll
        for (int i = 0; i < 32; i++) tot += g_part[i];
        g_scale = g[0] / sqrtf(tot);
        bool is64 = true;
        for (int i = 0; i < 32; i++)
            if (ne32[2 * i + 1] != 0) { is64 = false; break; }
        for (int i = 0; i < BATCH; i++) g_ne[i] = is64 ? ne32[2 * i] : ne32[i];
    }

    if (b < 16384) {                    // ---- uconv (hi only) ----
        uint32_t gid = b * 256 + t;
        int lane = gid & 31;
        int c    = (gid >> 5) & 31;
        int m16  = gid >> 10;
        int r    = m16 * 16 + (lane >> 2);
        int k0   = c * 16 + (lane & 3) * 2;
        const float* s0 = uf + (size_t)r * UFD;
        const float* s1 = uf + (size_t)(r + 8) * UFD;
        float2 a0 = *(const float2*)(s0 + k0);
        float2 a1 = *(const float2*)(s1 + k0);
        float2 a2 = *(const float2*)(s0 + k0 + 8);
        float2 a3 = *(const float2*)(s1 + k0 + 8);
        uint4 hi;
        hi.x = packh(a0.x, a0.y); hi.y = packh(a1.x, a1.y);
        hi.z = packh(a2.x, a2.y); hi.w = packh(a3.x, a3.y);
        g_ubf2[gid] = hi;
    } else if (b < 16448) {             // ---- vconv (hi only), 16384 gids ----
        uint32_t gid = (b - 16384) * 256 + t;
        int lane = gid & 31;
        int n8   = (gid >> 5) & 31;
        int c    = gid >> 10;           // 0..31 (wait: 16384/1024=16... recompute)
        // 16384 gids = 32c * 16n8 * 32lane: n8 is 16 wide here
        n8 = (gid >> 5) & 15;
        c  = gid >> 9;
        int n    = n8 * 8 + (lane >> 2);
        int k0   = c * 16 + (lane & 3) * 2;
        const float* src = v + (size_t)n * UFD;
        float2 f0 = *(const float2*)(src + k0);
        float2 f1 = *(const float2*)(src + k0 + 8);
        uint2 o;
        o.x = packh(f0.x, f0.y);
        o.y = packh(f1.x, f1.y);
        g_vbf2[(size_t)(c * 16 + n8) * 32 + lane] = o;
    } else {                            // ---- econv (hi only) ----
        uint32_t gid = (b - 16448) * 256 + t;
        int lane = gid & 31;
        int n8   = (gid >> 5) & 127;
        int c    = (gid >> 12) & 15;
        int z    = gid >> 16;
        int n    = n8 * 8 + (lane >> 2);
        int k0   = c * 16 + (lane & 3) * 2;
        const float* src = ef + ((size_t)z * ENUM + n) * EFD;
        float2 f0 = *(const float2*)(src + k0);
        float2 f1 = *(const float2*)(src + k0 + 8);
        uint2 o;
        o.x = packh(f0.x, f0.y);
        o.y = packh(f1.x, f1.y);
        g_ebf2[gid] = o;
    }
}

// ---------------------------------------------------------------------------
// proj GEMM: pure fp16 (1 MMA). relu(g_scale*(ufeat@v^T)+bias) -> g_pbf.
// Tile 128x128, 256 thr (2m x 4n warps, warp 64x32), 3-stage cp.async.
// NOTE: v B-frags cover 128 n per... v has 256 rows; n-tile n0 = blockIdx.x*128,
// chunk c's B slice = g_vbf2[(c*16 + n8base/8..)*32]. n8base = blockIdx.x*16,
// but v layout is [c][n8(16 of 128?)]. v rows = 256 -> n8 total 32 per chunk.
// Fixed: vconv above stores only 16 n8 per c (128 rows). Use 2 n-tiles via
// second half: we store v as [c][n8(16)] PER n-tile? -> simpler: vconv covers
// n8 0..15 only (rows 0..127). For rows 128..255 use second array half below.
// ---------------------------------------------------------------------------
// Correction: store v frags for all 256 rows: [c(32)][n8(32)][lane] uint2.
__device__ uint2 g_vbf2b[(size_t)32 * 32 * 32];

__global__ __launch_bounds__(256) void vconv_full(const float* __restrict__ v) {
    uint32_t gid = blockIdx.x * 256 + threadIdx.x;   // 32768
    int lane = gid & 31;
    int n8   = (gid >> 5) & 31;
    int c    = gid >> 10;
    int n    = n8 * 8 + (lane >> 2);
    int k0   = c * 16 + (lane & 3) * 2;
    const float* src = v + (size_t)n * UFD;
    float2 f0 = *(const float2*)(src + k0);
    float2 f1 = *(const float2*)(src + k0 + 8);
    uint2 o;
    o.x = packh(f0.x, f0.y);
    o.y = packh(f1.x, f1.y);
    g_vbf2b[(size_t)(c * 32 + n8) * 32 + lane] = o;
}

#define PSMEM_BYTES (3 * 512 * 16)   // 24 KB

__global__ __launch_bounds__(256, 2) void proj_gemm(const float* __restrict__ bias) {
    extern __shared__ uint4 su[];
    const uint32_t sbase = smem_u32(su);
    const int t = threadIdx.x;
    const int warp = t >> 5, lane = t & 31;
    const int warpM = warp >> 2, warpN = warp & 3;
    const int n0 = blockIdx.x * 128;
    const int m16base = blockIdx.y * 8;
    const int n8base = blockIdx.x * 16;

    float acc[4][4][4];
    #pragma unroll
    for (int i = 0; i < 4; i++)
        #pragma unroll
        for (int j = 0; j < 4; j++)
            #pragma unroll
            for (int r = 0; r < 4; r++) acc[i][j][r] = 0.f;

    constexpr int NCH = UFD / 16;   // 32

    auto issue = [&](int c) {
        const int s = ((unsigned)c) % 3;
        const uint32_t stb = sbase + s * 8192;
        {   // A: 256 uint4 (8 m16 x 32 lanes)
            int m16l = t >> 5, ln = t & 31;
            const uint4* src = g_ubf2 + (size_t)((m16base + m16l) * 32 + c) * 32 + ln;
            CP16(stb + t * 16, src);
        }
        {   // B: 256 uint4 = 512 uint2 (16 n8 x 32 lanes)
            const uint4* src = (const uint4*)(g_vbf2b + (size_t)(c * 32 + n8base) * 32) + t;
            CP16(stb + (256 + t) * 16, src);
        }
        CP_COMMIT();
    };

    issue(0);
    issue(1);
    #pragma unroll 1
    for (int c = 0; c < NCH; c++) {
        if (c == NCH - 1) CP_WAIT0(); else CP_WAIT1();
        __syncthreads();
        if (c + 2 < NCH) issue(c + 2);

        const uint4* st = su + ((unsigned)c % 3) * 512;
        const uint2* sB2 = (const uint2*)(st + 256);
        uint4 ah[4];
        uint2 bb[4];
        #pragma unroll
        for (int mt = 0; mt < 4; mt++)
            ah[mt] = st[(warpM * 4 + mt) * 32 + lane];
        #pragma unroll
        for (int nt = 0; nt < 4; nt++)
            bb[nt] = sB2[(warpN * 4 + nt) * 32 + lane];
        #pragma unroll
        for (int mt = 0; mt < 4; mt++)
            #pragma unroll
            for (int nt = 0; nt < 4; nt++)
                mma_f16(acc[mt][nt], (const uint32_t*)&ah[mt], (const uint32_t*)&bb[nt]);
    }

    // ---- epilogue: scale+bias+relu, pack into fp16-hi A-fragment form ----
    const int cb0 = n0 + warpN * 32 + (lane & 3) * 2;
    const float s = g_scale;
    #pragma unroll
    for (int mt = 0; mt < 4; mt++) {
        const int m16g = m16base + warpM * 4 + mt;
        #pragma unroll
        for (int j = 0; j < 2; j++) {
            const int cglob = (n0 >> 4) + warpN * 2 + j;
            float v0[4], v1[4];
            #pragma unroll
            for (int r = 0; r < 4; r++) {
                int col = cb0 + 2 * j * 8 + (r & 1);
                v0[r] = fmaxf(fmaf(s, acc[mt][2 * j][r], bias[col]), 0.f);
                v1[r] = fmaxf(fmaf(s, acc[mt][2 * j + 1][r], bias[col + 8]), 0.f);
            }
            uint4 hi;
            hi.x = packh(v0[0], v0[1]); hi.y = packh(v0[2], v0[3]);
            hi.z = packh(v1[0], v1[1]); hi.w = packh(v1[2], v1[3]);
            g_pbf[(size_t)m16g * 512 + cglob * 32 + lane] = hi;
        }
    }
}

// ---------------------------------------------------------------------------
// Fused logit GEMM + mask + softmax.  Pure fp16, 2 chunks (32 k) per step.
// CTA M=32, N=1024, 512 thr (1m x 16n warps), warp tile 32x64.
// SMEM (uint4): A [0,1024)  B stage s at [1024 + s*4096) (3 stages, 64KB each)
// ---------------------------------------------------------------------------
#define FSMEM_BYTES ((1024 + 3 * 4096) * 16)   // 212992

__global__ __launch_bounds__(512, 1) void logit_softmax(float* __restrict__ out) {
    extern __shared__ uint32_t sm[];
    const uint32_t sbase = smem_u32(sm);
    const int t = threadIdx.x;
    const int warp = t >> 5, lane = t & 31;
    const int z = blockIdx.y, m0 = blockIdx.x * 32;
    float* Ow = out + (size_t)z * UNUM * ENUM;

    // ---- A: cp.async pre-made hi fragments (1024 uint4) ----
    {
        const uint4* asrc = g_pbf + (size_t)(z * 64 + blockIdx.x * 2) * 512;
        #pragma unroll
        for (int i = 0; i < 2; i++) {
            int f = t + i * 512;
            CP16(sbase + f * 16, asrc + f);
        }
        CP_COMMIT();
    }

    float acc[2][8][4];
    #pragma unroll
    for (int mi = 0; mi < 2; mi++)
        #pragma unroll
        for (int nt = 0; nt < 8; nt++)
            #pragma unroll
            for (int r = 0; r < 4; r++) acc[mi][nt][r] = 0.f;

    const uint4* ebase = (const uint4*)(g_ebf2 + (size_t)z * 16 * 4096);
    auto issueB = [&](int ci) {        // ci = chunk-pair index 0..7
        const uint4* src = ebase + ci * 4096;
        const uint32_t bb = sbase + (1024 + ((unsigned)ci % 3) * 4096) * 16;
        #pragma unroll
        for (int i = 0; i < 8; i++) {
            int f = t + i * 512;
            CP16(bb + f * 16, src + f);
        }
        CP_COMMIT();
    };
    issueB(0);
    issueB(1);

    const uint4* sA4 = (const uint4*)sm;

    #pragma unroll 1
    for (int ci = 0; ci < 8; ci++) {
        if (ci == 7) CP_WAIT0(); else CP_WAIT1();
        __syncthreads();
        if (ci + 2 < 8) issueB(ci + 2);

        const uint2* Bu = (const uint2*)(sA4 + 1024 + ((unsigned)ci % 3) * 4096);
        #pragma unroll
        for (int cc = 0; cc < 2; cc++) {
            const int c = ci * 2 + cc;
            uint4 ah0 = sA4[c * 32 + lane];
            uint4 ah1 = sA4[512 + c * 32 + lane];
            #pragma unroll
            for (int nt = 0; nt < 8; nt++) {
                uint2 b = Bu[cc * 4096 + (warp * 8 + nt) * 32 + lane];
                uint32_t br[2] = { b.x, b.y };
                mma_f16(acc[0][nt], (const uint32_t*)&ah0, br);
                mma_f16(acc[1][nt], (const uint32_t*)&ah1, br);
            }
        }
    }

    // ---- scale + mask + per-lane row max ----
    const int ne = g_ne[z];
    const int lr = lane >> 2;
    float rmax[4] = { -FLT_MAX, -FLT_MAX, -FLT_MAX, -FLT_MAX };
    #pragma unroll
    for (int mi = 0; mi < 2; mi++)
        #pragma unroll
        for (int nt = 0; nt < 8; nt++) {
            int colb = warp * 64 + nt * 8 + (lane & 3) * 2;
            float p0 = (colb >= ne) ? 1e9f : 0.f;
            float p1 = (colb + 1 >= ne) ? 1e9f : 0.f;
            acc[mi][nt][0] = acc[mi][nt][0] * 0.0625f - p0;
            acc[mi][nt][1] = acc[mi][nt][1] * 0.0625f - p1;
            acc[mi][nt][2] = acc[mi][nt][2] * 0.0625f - p0;
            acc[mi][nt][3] = acc[mi][nt][3] * 0.0625f - p1;
            rmax[2 * mi]     = fmaxf(rmax[2 * mi],     fmaxf(acc[mi][nt][0], acc[mi][nt][1]));
            rmax[2 * mi + 1] = fmaxf(rmax[2 * mi + 1], fmaxf(acc[mi][nt][2], acc[mi][nt][3]));
        }
    #pragma unroll
    for (int j = 0; j < 4; j++) {
        rmax[j] = fmaxf(rmax[j], __shfl_xor_sync(0xffffffffu, rmax[j], 1));
        rmax[j] = fmaxf(rmax[j], __shfl_xor_sync(0xffffffffu, rmax[j], 2));
    }

    __syncthreads();                        // B stage 0 dead; reuse as scratch
    float* pmax = (float*)(sm + 4096);      // [32 rows][16 warps]
    float* psum = pmax + 512;
    if ((lane & 3) == 0) {
        #pragma unroll
        for (int j = 0; j < 4; j++) pmax[(lr + j * 8) * 16 + warp] = rmax[j];
    }
    __syncthreads();
    float rm[4];
    #pragma unroll
    for (int j = 0; j < 4; j++) {
        float m = pmax[(lr + j * 8) * 16];
        #pragma unroll
        for (int w = 1; w < 16; w++) m = fmaxf(m, pmax[(lr + j * 8) * 16 + w]);
        rm[j] = m;
    }

    float rs[4] = { 0.f, 0.f, 0.f, 0.f };
    #pragma unroll
    for (int mi = 0; mi < 2; mi++)
        #pragma unroll
        for (int nt = 0; nt < 8; nt++) {
            acc[mi][nt][0] = __expf(acc[mi][nt][0] - rm[2 * mi]);
            acc[mi][nt][1] = __expf(acc[mi][nt][1] - rm[2 * mi]);
            acc[mi][nt][2] = __expf(acc[mi][nt][2] - rm[2 * mi + 1]);
            acc[mi][nt][3] = __expf(acc[mi][nt][3] - rm[2 * mi + 1]);
            rs[2 * mi]     += acc[mi][nt][0] + acc[mi][nt][1];
            rs[2 * mi + 1] += acc[mi][nt][2] + acc[mi][nt][3];
        }
    #pragma unroll
    for (int j = 0; j < 4; j++) {
        rs[j] += __shfl_xor_sync(0xffffffffu, rs[j], 1);
        rs[j] += __shfl_xor_sync(0xffffffffu, rs[j], 2);
    }
    if ((lane & 3) == 0) {
        #pragma unroll
        for (int j = 0; j < 4; j++) psum[(lr + j * 8) * 16 + warp] = rs[j];
    }
    __syncthreads();
    float inv[4];
    #pragma unroll
    for (int j = 0; j < 4; j++) {
        float s = 0.f;
        #pragma unroll
        for (int w = 0; w < 16; w++) s += psum[(lr + j * 8) * 16 + w];
        inv[j] = 1.f / s;
    }

    // ---- normalize + store ----
    #pragma unroll
    for (int mi = 0; mi < 2; mi++) {
        float* r0 = Ow + (size_t)(m0 + mi * 16 + lr) * ENUM;
        float* r1 = Ow + (size_t)(m0 + mi * 16 + lr + 8) * ENUM;
        #pragma unroll
        for (int nt = 0; nt < 8; nt++) {
            int colb = warp * 64 + nt * 8 + (lane & 3) * 2;
            *(float2*)(r0 + colb) =
                make_float2(acc[mi][nt][0] * inv[2 * mi], acc[mi][nt][1] * inv[2 * mi]);
            *(float2*)(r1 + colb) =
                make_float2(acc[mi][nt][2] * inv[2 * mi + 1], acc[mi][nt][3] * inv[2 * mi + 1]);
        }
    }
}

// ---------------------------------------------------------------------------
extern "C" void kernel_launch(void* const* d_in, const int* in_sizes, int n_in,
                              void* d_out, int out_size) {
    const float* ufeat = (const float*)d_in[0];   // [64,1024,512]
    const float* efeat = (const float*)d_in[1];   // [64,1024,256]
    const int*   neptr = (const int*)d_in[2];     // [64] int32 or int64
    const float* v     = (const float*)d_in[3];   // [256,512]
    const float* g     = (const float*)d_in[4];   // scalar
    const float* bias  = (const float*)d_in[5];   // [256]
    float* out = (float*)d_out;                   // [64,1024,1024]

    cudaFuncSetAttribute(proj_gemm, cudaFuncAttributeMaxDynamicSharedMemorySize, PSMEM_BYTES);
    cudaFuncSetAttribute(logit_softmax, cudaFuncAttributeMaxDynamicSharedMemorySize, FSMEM_BYTES);

    prep_partial<<<32, 1024>>>(v);
    vconv_full<<<128, 256>>>(v);
    conv_all<<<32832, 256>>>(ufeat, v, efeat, g, neptr);   // 16384 u + 64 unused-v + 16384 e
    proj_gemm<<<dim3(2, 512), 256, PSMEM_BYTES>>>(bias);
    logit_softmax<<<dim3(UNUM / 32, BATCH), 512, FSMEM_BYTES>>>(out);
}